// round 2
// baseline (speedup 1.0000x reference)
#include <cuda_runtime.h>

#define B_ 2
#define L_ 2048
#define D_ 1024
#define H_ 16
#define DH_ 64
#define M_ (B_*L_)
#define OUT_ELEMS (B_*L_*D_)
#define ATTN_ELEMS ((size_t)B_*H_*L_*L_)

// -------- scratch (static device arrays; no cudaMalloc allowed) --------
__device__ float g_Q[B_*H_*L_*DH_];
__device__ float g_K[B_*H_*L_*DH_];
__device__ float g_V[B_*H_*L_*DH_];
__device__ float g_sal[B_*H_*L_];
__device__ float g_ctx[B_*L_*D_];

// -------- fast exp on the FMA pipe (avoid MUFU.EX2 throughput wall) --------
__device__ __forceinline__ float fast_exp(float x) {
    x = fminf(fmaxf(x, -80.f), 80.f);
    float y = x * 1.4426950408889634f;
    float t = y + 12582912.0f;            // round-to-nearest magic
    float n = t - 12582912.0f;
    float f = y - n;
    float p = 1.3333558146428443e-3f;
    p = fmaf(p, f, 9.6181291076284772e-3f);
    p = fmaf(p, f, 5.5504108664821580e-2f);
    p = fmaf(p, f, 2.4022650695910072e-1f);
    p = fmaf(p, f, 6.9314718055994531e-1f);
    p = fmaf(p, f, 1.0f);
    int ni = __float2int_rn(n);
    return __int_as_float(__float_as_int(p) + (ni << 23));
}

// ============================================================================
// SGEMM (NT): C[m,n] = sum_k A[m,k]*W[n,k] + bias[n]
// A:[M,1024] row-major, W:[1024,1024] row-major (torch Linear [out,in]).
// 128x128 tile, BK=8, 256 threads, 8x8 microtile.
// headed=1: scatter into [b,h,l,dh] (QKV). headed=0: plain [m,n].
// ============================================================================
__global__ void __launch_bounds__(256) sgemm_nt128(
    const float* __restrict__ A, const float* __restrict__ W,
    const float* __restrict__ bias, float* __restrict__ C, int headed)
{
    __shared__ float As[8][128];
    __shared__ float Bs[8][128];
    const int tid = threadIdx.x;
    const int m0 = blockIdx.y * 128;
    const int n0 = blockIdx.x * 128;
    const int lr = tid >> 1;
    const int lc = (tid & 1) * 4;
    const int ty = tid >> 4;
    const int tx = tid & 15;

    float acc[8][8];
#pragma unroll
    for (int i = 0; i < 8; ++i)
#pragma unroll
        for (int j = 0; j < 8; ++j) acc[i][j] = 0.f;

    for (int k0 = 0; k0 < 1024; k0 += 8) {
        float4 av = *(const float4*)(A + (size_t)(m0 + lr) * 1024 + k0 + lc);
        float4 bv = *(const float4*)(W + (size_t)(n0 + lr) * 1024 + k0 + lc);
        __syncthreads();
        As[lc + 0][lr] = av.x; As[lc + 1][lr] = av.y;
        As[lc + 2][lr] = av.z; As[lc + 3][lr] = av.w;
        Bs[lc + 0][lr] = bv.x; Bs[lc + 1][lr] = bv.y;
        Bs[lc + 2][lr] = bv.z; Bs[lc + 3][lr] = bv.w;
        __syncthreads();
#pragma unroll
        for (int kk = 0; kk < 8; ++kk) {
            float a[8], bb[8];
#pragma unroll
            for (int i = 0; i < 8; ++i) a[i] = As[kk][ty * 8 + i];
#pragma unroll
            for (int j = 0; j < 8; ++j) bb[j] = Bs[kk][tx * 8 + j];
#pragma unroll
            for (int i = 0; i < 8; ++i)
#pragma unroll
                for (int j = 0; j < 8; ++j)
                    acc[i][j] = fmaf(a[i], bb[j], acc[i][j]);
        }
    }

    float bb[8];
    const int nb = n0 + tx * 8;
#pragma unroll
    for (int j = 0; j < 8; ++j) bb[j] = bias[nb + j];

#pragma unroll
    for (int i = 0; i < 8; ++i) {
        int m = m0 + ty * 8 + i;
        float4 v0 = make_float4(acc[i][0] + bb[0], acc[i][1] + bb[1],
                                acc[i][2] + bb[2], acc[i][3] + bb[3]);
        float4 v1 = make_float4(acc[i][4] + bb[4], acc[i][5] + bb[5],
                                acc[i][6] + bb[6], acc[i][7] + bb[7]);
        float* cp;
        if (!headed) {
            cp = C + (size_t)m * 1024 + nb;
        } else {
            int b = m >> 11, l = m & 2047;
            int h = nb >> 6, dh = nb & 63;
            cp = C + (size_t)(((b << 4) + h) * 2048 + l) * 64 + dh;
        }
        *(float4*)cp = v0;
        *(float4*)(cp + 4) = v1;
    }
}

// ============================================================================
// Saliency Conv1d(D->H, k=3, pad=1): sal[b,h,l]
// Block = (b, 16-l tile), 256 threads, 18 src rows staged in SMEM.
// ============================================================================
#define CONV_SMEM (18 * 1028 * 4)
__global__ void __launch_bounds__(256) conv_sal_kernel(
    const float* __restrict__ src, const float* __restrict__ cw,
    const float* __restrict__ cb, float* __restrict__ sal)
{
    extern __shared__ float ss[];   // [18][1028]
    const int bid = blockIdx.x;
    const int b = bid >> 7, lt = bid & 127;
    const int l0 = lt * 16;
    const int tid = threadIdx.x;

#pragma unroll
    for (int it = 0; it < 18; ++it) {
        int idx = it * 256 + tid;
        int row = idx >> 8;
        int c4 = idx & 255;
        int gl = l0 + row - 1;
        float4 v = make_float4(0.f, 0.f, 0.f, 0.f);
        if (gl >= 0 && gl < L_)
            v = *(const float4*)(src + ((size_t)b * L_ + gl) * D_ + c4 * 4);
        *(float4*)(ss + row * 1028 + c4 * 4) = v;
    }
    __syncthreads();

    const int h = tid >> 4, li = tid & 15;
    const float* wp = cw + (size_t)h * D_ * 3;
    float acc = 0.f;
#pragma unroll 4
    for (int d = 0; d < D_; ++d) {
        float w0 = wp[d * 3 + 0], w1 = wp[d * 3 + 1], w2 = wp[d * 3 + 2];
        acc = fmaf(ss[(li + 0) * 1028 + d], w0, acc);
        acc = fmaf(ss[(li + 1) * 1028 + d], w1, acc);
        acc = fmaf(ss[(li + 2) * 1028 + d], w2, acc);
    }
    sal[(size_t)(b * H_ + h) * L_ + l0 + li] = acc + cb[h];
}

// ============================================================================
// Fused attention per block (bh, 16 q-rows):
//   S = Q K^T/8 + sal -> exp -> rowsum -> normalize -> attn write -> P@V
// SMEM floats: sP[16][2048]@0, sK[256][65]@32768 (reused sV[128][68],
// red[4][1024]@41472), sQ[16][64]@49408, sSum@50432, sInv@50688
// ============================================================================
#define SMEM_FLOATS 50704
#define ATTN_SMEM (SMEM_FLOATS * 4)

__global__ void __launch_bounds__(256) attn_kernel(
    const float* __restrict__ Q, const float* __restrict__ K,
    const float* __restrict__ V, const float* __restrict__ sal,
    float* __restrict__ ctx, float* __restrict__ attn)
{
    extern __shared__ float sm[];
    float* sP   = sm;
    float* sK   = sm + 32768;
    float* sV   = sm + 32768;
    float* red  = sm + 41472;
    float* sQ   = sm + 49408;
    float* sSum = sm + 50432;
    float* sInv = sm + 50688;

    const int tid = threadIdx.x;
    const int q0 = blockIdx.x * 16;
    const int bh = blockIdx.y;
    const size_t base = (size_t)bh * (L_ * DH_);
    const float* salRow = sal + (size_t)bh * L_;

    ((float4*)sQ)[tid] = ((const float4*)(Q + base + (size_t)q0 * DH_))[tid];
    __syncthreads();

    const int ty = tid >> 6;
    const int tx = tid & 63;

    // ---- Phase 1: scores ----
    for (int kt = 0; kt < 8; ++kt) {
        const int kbase = kt * 256;
        const float4* Kg = (const float4*)(K + base + (size_t)kbase * DH_);
#pragma unroll
        for (int it = 0; it < 16; ++it) {
            int idx = it * 256 + tid;
            int k = idx >> 4, dq = idx & 15;
            float4 v = Kg[idx];
            float* dst = sK + k * 65 + dq * 4;
            dst[0] = v.x; dst[1] = v.y; dst[2] = v.z; dst[3] = v.w;
        }
        __syncthreads();

        float acc[4][4];
#pragma unroll
        for (int i = 0; i < 4; ++i)
#pragma unroll
            for (int j = 0; j < 4; ++j) acc[i][j] = 0.f;

#pragma unroll 8
        for (int d = 0; d < 64; ++d) {
            float qv[4], kv[4];
#pragma unroll
            for (int qq = 0; qq < 4; ++qq) qv[qq] = sQ[(ty * 4 + qq) * 64 + d];
#pragma unroll
            for (int i = 0; i < 4; ++i) kv[i] = sK[(tx + (i << 6)) * 65 + d];
#pragma unroll
            for (int qq = 0; qq < 4; ++qq)
#pragma unroll
                for (int i = 0; i < 4; ++i)
                    acc[qq][i] = fmaf(qv[qq], kv[i], acc[qq][i]);
        }

#pragma unroll
        for (int i = 0; i < 4; ++i) {
            int kg = kbase + tx + (i << 6);
            float sv = salRow[kg];
#pragma unroll
            for (int qq = 0; qq < 4; ++qq)
                sP[(ty * 4 + qq) * 2048 + kg] = fmaf(acc[qq][i], 0.125f, sv);
        }
        __syncthreads();
    }

    // ---- softmax: exp + rowsum ----
    {
        int r = tid >> 4, seg = tid & 15;
        float* rowp = sP + r * 2048;
        float psum = 0.f;
#pragma unroll 4
        for (int j = 0; j < 128; ++j) {
            int col = seg + (j << 4);
            float e = fast_exp(rowp[col]);
            rowp[col] = e;
            psum += e;
        }
        sSum[r * 16 + seg] = psum;
    }
    __syncthreads();
    if (tid < 16) {
        float s = 0.f;
#pragma unroll
        for (int i = 0; i < 16; ++i) s += sSum[tid * 16 + i];
        sInv[tid] = 1.f / s;
    }
    __syncthreads();

    // ---- normalize + single coalesced attn write ----
    {
        int w = tid >> 5, lane = tid & 31;
#pragma unroll
        for (int rr = 0; rr < 2; ++rr) {
            int r = w * 2 + rr;
            float inv = sInv[r];
            float4* rowP = (float4*)(sP + r * 2048);
            float4* gout = (float4*)(attn + ((size_t)bh * L_ + q0 + r) * L_);
#pragma unroll 4
            for (int it = 0; it < 16; ++it) {
                int c = lane + it * 32;
                float4 v = rowP[c];
                v.x *= inv; v.y *= inv; v.z *= inv; v.w *= inv;
                rowP[c] = v;
                gout[c] = v;
            }
        }
    }
    __syncthreads();

    // ---- Phase 2: ctx = P @ V, 4-way k-split ----
    const int g = ty;
    const int s = tx;
    const int qb  = (s >> 4) * 4;
    const int dh4 = (s & 15) * 4;
    float4 a0 = make_float4(0, 0, 0, 0), a1 = a0, a2 = a0, a3 = a0;

    for (int vt = 0; vt < 16; ++vt) {
        const float4* Vg = (const float4*)(V + base + (size_t)vt * 128 * DH_);
#pragma unroll
        for (int it = 0; it < 8; ++it) {
            int idx = it * 256 + tid;
            int k = idx >> 4, dq = idx & 15;
            *(float4*)(sV + k * 68 + dq * 4) = Vg[idx];
        }
        __syncthreads();
#pragma unroll 4
        for (int kk = 0; kk < 32; ++kk) {
            int kl = (g << 5) + kk;
            float4 vv = *(const float4*)(sV + kl * 68 + dh4);
            const float* pcol = sP + (vt * 128 + kl);
            float p0 = pcol[(qb + 0) * 2048];
            float p1 = pcol[(qb + 1) * 2048];
            float p2 = pcol[(qb + 2) * 2048];
            float p3 = pcol[(qb + 3) * 2048];
            a0.x = fmaf(p0, vv.x, a0.x); a0.y = fmaf(p0, vv.y, a0.y);
            a0.z = fmaf(p0, vv.z, a0.z); a0.w = fmaf(p0, vv.w, a0.w);
            a1.x = fmaf(p1, vv.x, a1.x); a1.y = fmaf(p1, vv.y, a1.y);
            a1.z = fmaf(p1, vv.z, a1.z); a1.w = fmaf(p1, vv.w, a1.w);
            a2.x = fmaf(p2, vv.x, a2.x); a2.y = fmaf(p2, vv.y, a2.y);
            a2.z = fmaf(p2, vv.z, a2.z); a2.w = fmaf(p2, vv.w, a2.w);
            a3.x = fmaf(p3, vv.x, a3.x); a3.y = fmaf(p3, vv.y, a3.y);
            a3.z = fmaf(p3, vv.z, a3.z); a3.w = fmaf(p3, vv.w, a3.w);
        }
        __syncthreads();
    }

    *(float4*)(red + g * 1024 + s * 16 + 0)  = a0;
    *(float4*)(red + g * 1024 + s * 16 + 4)  = a1;
    *(float4*)(red + g * 1024 + s * 16 + 8)  = a2;
    *(float4*)(red + g * 1024 + s * 16 + 12) = a3;
    __syncthreads();
    {
        int s2 = tid >> 2, c = tid & 3;
        float4 sum = make_float4(0, 0, 0, 0);
#pragma unroll
        for (int gg = 0; gg < 4; ++gg) {
            const float4 v = *(const float4*)(red + gg * 1024 + s2 * 16 + c * 4);
            sum.x += v.x; sum.y += v.y; sum.z += v.z; sum.w += v.w;
        }
        int q  = ((s2 >> 4) << 2) + c;
        int dh = (s2 & 15) << 2;
        int b = bh >> 4, h = bh & 15;
        int l = q0 + q;
        *(float4*)(ctx + ((size_t)(b * L_ + l)) * D_ + h * DH_ + dh) = sum;
    }
}

// ============================================================================
// host launcher
// ============================================================================
extern "C" void kernel_launch(void* const* d_in, const int* in_sizes, int n_in,
                              void* d_out, int out_size)
{
    const float* src = (const float*)d_in[0];
    const float* Wq  = (const float*)d_in[1];
    const float* bq  = (const float*)d_in[2];
    const float* Wk  = (const float*)d_in[3];
    const float* bk  = (const float*)d_in[4];
    const float* Wv  = (const float*)d_in[5];
    const float* bv  = (const float*)d_in[6];
    const float* Wo  = (const float*)d_in[7];
    const float* bo  = (const float*)d_in[8];
    const float* cw  = (const float*)d_in[9];
    const float* cb  = (const float*)d_in[10];

    float* out      = (float*)d_out;
    float* attn_out = out + OUT_ELEMS;

    float *Qp, *Kp, *Vp, *salp, *ctxp;
    cudaGetSymbolAddress((void**)&Qp,   g_Q);
    cudaGetSymbolAddress((void**)&Kp,   g_K);
    cudaGetSymbolAddress((void**)&Vp,   g_V);
    cudaGetSymbolAddress((void**)&salp, g_sal);
    cudaGetSymbolAddress((void**)&ctxp, g_ctx);

    cudaFuncSetAttribute(conv_sal_kernel,
        cudaFuncAttributeMaxDynamicSharedMemorySize, CONV_SMEM);
    cudaFuncSetAttribute(attn_kernel,
        cudaFuncAttributeMaxDynamicSharedMemorySize, ATTN_SMEM);

    // saliency conv
    conv_sal_kernel<<<B_ * 128, 256, CONV_SMEM>>>(src, cw, cb, salp);

    // QKV projections -> [b,h,l,dh]
    dim3 ggrid(8, 32);
    sgemm_nt128<<<ggrid, 256>>>(src, Wq, bq, Qp, 1);
    sgemm_nt128<<<ggrid, 256>>>(src, Wk, bk, Kp, 1);
    sgemm_nt128<<<ggrid, 256>>>(src, Wv, bv, Vp, 1);

    // fused attention (writes attn + ctx)
    dim3 agrid(L_ / 16, B_ * H_);
    attn_kernel<<<agrid, 256, ATTN_SMEM>>>(Qp, Kp, Vp, salp, ctxp, attn_out);

    // output projection -> d_out
    sgemm_nt128<<<ggrid, 256>>>(ctxp, Wo, bo, out, 0);
}

// round 5
// speedup vs baseline: 1.2232x; 1.2232x over previous
#include <cuda_runtime.h>
#include <cuda_bf16.h>
#include <cstdint>

#define B_ 2
#define L_ 2048
#define D_ 1024
#define H_ 16
#define DH_ 64
#define M_ (B_*L_)
#define OUT_ELEMS (B_*L_*D_)

// -------- scratch (static device arrays; no cudaMalloc allowed) --------
__device__ float g_Q[B_*H_*L_*DH_];
__device__ float g_K[B_*H_*L_*DH_];
__device__ float g_V[B_*H_*L_*DH_];
__device__ float g_sal[B_*H_*L_];
__device__ float g_ctx[B_*L_*D_];
__device__ __nv_bfloat16 g_Ahi[M_*D_];
__device__ __nv_bfloat16 g_Alo[M_*D_];
__device__ __nv_bfloat16 g_Whi[4][D_*D_];
__device__ __nv_bfloat16 g_Wlo[4][D_*D_];

__device__ __forceinline__ uint32_t smem_u32(const void* p) {
    uint32_t a;
    asm("{ .reg .u64 t; cvta.to.shared.u64 t, %1; cvt.u32.u64 %0, t; }"
        : "=r"(a) : "l"(p));
    return a;
}

// -------- fast exp on the FMA pipe (avoid MUFU.EX2 throughput wall) --------
__device__ __forceinline__ float fast_exp(float x) {
    x = fminf(fmaxf(x, -80.f), 80.f);
    float y = x * 1.4426950408889634f;
    float t = y + 12582912.0f;
    float n = t - 12582912.0f;
    float f = y - n;
    float p = 1.3333558146428443e-3f;
    p = fmaf(p, f, 9.6181291076284772e-3f);
    p = fmaf(p, f, 5.5504108664821580e-2f);
    p = fmaf(p, f, 2.4022650695910072e-1f);
    p = fmaf(p, f, 6.9314718055994531e-1f);
    p = fmaf(p, f, 1.0f);
    int ni = __float2int_rn(n);
    return __int_as_float(__float_as_int(p) + (ni << 23));
}

// ============================================================================
// fp32 -> bf16 hi/lo split (vectorized)
// ============================================================================
__global__ void __launch_bounds__(256) cvt_split(
    const float* __restrict__ x, __nv_bfloat16* __restrict__ hi,
    __nv_bfloat16* __restrict__ lo, int n4)
{
    int i = blockIdx.x * blockDim.x + threadIdx.x;
    if (i >= n4) return;
    float4 v = ((const float4*)x)[i];
    __nv_bfloat16 h0 = __float2bfloat16(v.x);
    __nv_bfloat16 h1 = __float2bfloat16(v.y);
    __nv_bfloat16 h2 = __float2bfloat16(v.z);
    __nv_bfloat16 h3 = __float2bfloat16(v.w);
    __nv_bfloat162* hp = (__nv_bfloat162*)hi;
    __nv_bfloat162* lp = (__nv_bfloat162*)lo;
    hp[2 * i]     = __nv_bfloat162(h0, h1);
    hp[2 * i + 1] = __nv_bfloat162(h2, h3);
    lp[2 * i]     = __nv_bfloat162(__float2bfloat16(v.x - __bfloat162float(h0)),
                                   __float2bfloat16(v.y - __bfloat162float(h1)));
    lp[2 * i + 1] = __nv_bfloat162(__float2bfloat16(v.z - __bfloat162float(h2)),
                                   __float2bfloat16(v.w - __bfloat162float(h3)));
}

// ============================================================================
// mma.sync bf16x3 GEMM: C[m,n] = sum_k A[m,k]*W[n,k] + bias[n]
// C = AhBh + AhBl + AlBh, fp32 register accumulators.
// 128x128 block tile, 8 warps (64x32 each), BK=32, ldmatrix operands.
// SMEM: 4 tiles of [128][40] bf16 (pad stride 40 -> conflict-free ldmatrix).
// ============================================================================
#define TSTRIDE 40
#define GEMM_SMEM (4 * 128 * TSTRIDE * 2)

__device__ __forceinline__ void ldm_x4(uint32_t* r, uint32_t addr) {
    asm volatile("ldmatrix.sync.aligned.m8n8.x4.shared.b16 {%0,%1,%2,%3}, [%4];"
        : "=r"(r[0]), "=r"(r[1]), "=r"(r[2]), "=r"(r[3]) : "r"(addr));
}
__device__ __forceinline__ void ldm_x2(uint32_t* r, uint32_t addr) {
    asm volatile("ldmatrix.sync.aligned.m8n8.x2.shared.b16 {%0,%1}, [%2];"
        : "=r"(r[0]), "=r"(r[1]) : "r"(addr));
}
__device__ __forceinline__ void mma16816(float* c, const uint32_t* a, const uint32_t* b) {
    asm volatile(
        "mma.sync.aligned.m16n8k16.row.col.f32.bf16.bf16.f32 "
        "{%0,%1,%2,%3}, {%4,%5,%6,%7}, {%8,%9}, {%0,%1,%2,%3};"
        : "+f"(c[0]), "+f"(c[1]), "+f"(c[2]), "+f"(c[3])
        : "r"(a[0]), "r"(a[1]), "r"(a[2]), "r"(a[3]), "r"(b[0]), "r"(b[1]));
}

__global__ void __launch_bounds__(256) mma_gemm_bf16x3(
    const __nv_bfloat16* __restrict__ Ah, const __nv_bfloat16* __restrict__ Al,
    const __nv_bfloat16* __restrict__ Bh, const __nv_bfloat16* __restrict__ Bl,
    const float* __restrict__ bias, float* __restrict__ C, int headed)
{
    extern __shared__ __align__(128) __nv_bfloat16 smx[];
    __nv_bfloat16* sAh = smx;
    __nv_bfloat16* sAl = smx + 128 * TSTRIDE;
    __nv_bfloat16* sBh = smx + 2 * 128 * TSTRIDE;
    __nv_bfloat16* sBl = smx + 3 * 128 * TSTRIDE;

    const int tid = threadIdx.x;
    const int wid = tid >> 5;
    const int lane = tid & 31;
    const int wm = (wid & 1) * 64;    // warp m offset within tile
    const int wn = (wid >> 1) * 32;   // warp n offset within tile
    const int m0 = blockIdx.y * 128;
    const int n0 = blockIdx.x * 128;

    float c[4][4][4];
#pragma unroll
    for (int i = 0; i < 4; ++i)
#pragma unroll
        for (int j = 0; j < 4; ++j)
#pragma unroll
            for (int r = 0; r < 4; ++r) c[i][j][r] = 0.f;

    // ldmatrix source addresses (elements)
    const uint32_t aBase = smem_u32(sAh);
    const int arow = lane & 15, acol = (lane >> 4) << 3;
    const int brow = lane & 7,  bcol = ((lane >> 3) & 1) << 3;

    for (int k0 = 0; k0 < 1024; k0 += 32) {
        // ---- stage 4 x (128 x 32) bf16 tiles ----
#pragma unroll
        for (int t = 0; t < 2; ++t) {
            int idx = t * 256 + tid;          // 0..511
            int row = idx >> 2, sub = idx & 3;
            size_t ga = (size_t)(m0 + row) * D_ + k0 + sub * 8;
            size_t gb = (size_t)(n0 + row) * D_ + k0 + sub * 8;
            int so = row * TSTRIDE + sub * 8;
            *(uint4*)(sAh + so) = *(const uint4*)(Ah + ga);
            *(uint4*)(sAl + so) = *(const uint4*)(Al + ga);
            *(uint4*)(sBh + so) = *(const uint4*)(Bh + gb);
            *(uint4*)(sBl + so) = *(const uint4*)(Bl + gb);
        }
        __syncthreads();

#pragma unroll
        for (int ks = 0; ks < 2; ++ks) {
            const int kk = ks * 16;
            uint32_t ah[4][4], al[4][4];
#pragma unroll
            for (int mt = 0; mt < 4; ++mt) {
                uint32_t off = (uint32_t)((wm + mt * 16 + arow) * TSTRIDE + kk + acol) * 2;
                ldm_x4(ah[mt], aBase + off);
                ldm_x4(al[mt], aBase + (uint32_t)(128 * TSTRIDE * 2) + off);
            }
#pragma unroll
            for (int nt = 0; nt < 4; ++nt) {
                uint32_t boff = (uint32_t)((wn + nt * 8 + brow) * TSTRIDE + kk + bcol) * 2;
                uint32_t bh[2], bl[2];
                ldm_x2(bh, aBase + (uint32_t)(2 * 128 * TSTRIDE * 2) + boff);
                ldm_x2(bl, aBase + (uint32_t)(3 * 128 * TSTRIDE * 2) + boff);
#pragma unroll
                for (int mt = 0; mt < 4; ++mt) {
                    mma16816(c[mt][nt], ah[mt], bh);
                    mma16816(c[mt][nt], ah[mt], bl);
                    mma16816(c[mt][nt], al[mt], bh);
                }
            }
        }
        __syncthreads();
    }

    // ---- epilogue: c[mt][nt] regs -> global (+bias) ----
    const int rl = lane >> 2;          // 0..7
    const int cl = (lane & 3) * 2;     // 0,2,4,6
#pragma unroll
    for (int mt = 0; mt < 4; ++mt) {
#pragma unroll
        for (int half = 0; half < 2; ++half) {
            int m = m0 + wm + mt * 16 + rl + half * 8;
            int b = m >> 11, l = m & 2047;
#pragma unroll
            for (int nt = 0; nt < 4; ++nt) {
                int n = n0 + wn + nt * 8 + cl;
                float v0 = c[mt][nt][half * 2 + 0] + bias[n];
                float v1 = c[mt][nt][half * 2 + 1] + bias[n + 1];
                float* cp;
                if (!headed) {
                    cp = C + (size_t)m * D_ + n;
                } else {
                    int h = n >> 6, dh = n & 63;
                    cp = C + (size_t)(((b << 4) + h) * 2048 + l) * 64 + dh;
                }
                *(float2*)cp = make_float2(v0, v1);
            }
        }
    }
}

// ============================================================================
// Saliency Conv1d(D->H, k=3, pad=1): sal[b,h,l]
// ============================================================================
#define CONV_SMEM (18 * 1028 * 4)
__global__ void __launch_bounds__(256) conv_sal_kernel(
    const float* __restrict__ src, const float* __restrict__ cw,
    const float* __restrict__ cb, float* __restrict__ sal)
{
    extern __shared__ float ss[];
    const int bid = blockIdx.x;
    const int b = bid >> 7, lt = bid & 127;
    const int l0 = lt * 16;
    const int tid = threadIdx.x;

#pragma unroll
    for (int it = 0; it < 18; ++it) {
        int idx = it * 256 + tid;
        int row = idx >> 8;
        int c4 = idx & 255;
        int gl = l0 + row - 1;
        float4 v = make_float4(0.f, 0.f, 0.f, 0.f);
        if (gl >= 0 && gl < L_)
            v = *(const float4*)(src + ((size_t)b * L_ + gl) * D_ + c4 * 4);
        *(float4*)(ss + row * 1028 + c4 * 4) = v;
    }
    __syncthreads();

    const int h = tid >> 4, li = tid & 15;
    const float* wp = cw + (size_t)h * D_ * 3;
    float acc = 0.f;
#pragma unroll 4
    for (int d = 0; d < D_; ++d) {
        float w0 = wp[d * 3 + 0], w1 = wp[d * 3 + 1], w2 = wp[d * 3 + 2];
        acc = fmaf(ss[(li + 0) * 1028 + d], w0, acc);
        acc = fmaf(ss[(li + 1) * 1028 + d], w1, acc);
        acc = fmaf(ss[(li + 2) * 1028 + d], w2, acc);
    }
    sal[(size_t)(b * H_ + h) * L_ + l0 + li] = acc + cb[h];
}

// ============================================================================
// Fused attention per block (bh, 16 q-rows) — unchanged (passing since R2)
// ============================================================================
#define SMEM_FLOATS 50704
#define ATTN_SMEM (SMEM_FLOATS * 4)

__global__ void __launch_bounds__(256) attn_kernel(
    const float* __restrict__ Q, const float* __restrict__ K,
    const float* __restrict__ V, const float* __restrict__ sal,
    float* __restrict__ ctx, float* __restrict__ attn)
{
    extern __shared__ float sm[];
    float* sP   = sm;
    float* sK   = sm + 32768;
    float* sV   = sm + 32768;
    float* red  = sm + 41472;
    float* sQ   = sm + 49408;
    float* sSum = sm + 50432;
    float* sInv = sm + 50688;

    const int tid = threadIdx.x;
    const int q0 = blockIdx.x * 16;
    const int bh = blockIdx.y;
    const size_t base = (size_t)bh * (L_ * DH_);
    const float* salRow = sal + (size_t)bh * L_;

    ((float4*)sQ)[tid] = ((const float4*)(Q + base + (size_t)q0 * DH_))[tid];
    __syncthreads();

    const int ty = tid >> 6;
    const int tx = tid & 63;

    for (int kt = 0; kt < 8; ++kt) {
        const int kbase = kt * 256;
        const float4* Kg = (const float4*)(K + base + (size_t)kbase * DH_);
#pragma unroll
        for (int it = 0; it < 16; ++it) {
            int idx = it * 256 + tid;
            int k = idx >> 4, dq = idx & 15;
            float4 v = Kg[idx];
            float* dst = sK + k * 65 + dq * 4;
            dst[0] = v.x; dst[1] = v.y; dst[2] = v.z; dst[3] = v.w;
        }
        __syncthreads();

        float acc[4][4];
#pragma unroll
        for (int i = 0; i < 4; ++i)
#pragma unroll
            for (int j = 0; j < 4; ++j) acc[i][j] = 0.f;

#pragma unroll 8
        for (int d = 0; d < 64; ++d) {
            float qv[4], kv[4];
#pragma unroll
            for (int qq = 0; qq < 4; ++qq) qv[qq] = sQ[(ty * 4 + qq) * 64 + d];
#pragma unroll
            for (int i = 0; i < 4; ++i) kv[i] = sK[(tx + (i << 6)) * 65 + d];
#pragma unroll
            for (int qq = 0; qq < 4; ++qq)
#pragma unroll
                for (int i = 0; i < 4; ++i)
                    acc[qq][i] = fmaf(qv[qq], kv[i], acc[qq][i]);
        }

#pragma unroll
        for (int i = 0; i < 4; ++i) {
            int kg = kbase + tx + (i << 6);
            float sv = salRow[kg];
#pragma unroll
            for (int qq = 0; qq < 4; ++qq)
                sP[(ty * 4 + qq) * 2048 + kg] = fmaf(acc[qq][i], 0.125f, sv);
        }
        __syncthreads();
    }

    {
        int r = tid >> 4, seg = tid & 15;
        float* rowp = sP + r * 2048;
        float psum = 0.f;
#pragma unroll 4
        for (int j = 0; j < 128; ++j) {
            int col = seg + (j << 4);
            float e = fast_exp(rowp[col]);
            rowp[col] = e;
            psum += e;
        }
        sSum[r * 16 + seg] = psum;
    }
    __syncthreads();
    if (tid < 16) {
        float s = 0.f;
#pragma unroll
        for (int i = 0; i < 16; ++i) s += sSum[tid * 16 + i];
        sInv[tid] = 1.f / s;
    }
    __syncthreads();

    {
        int w = tid >> 5, lane = tid & 31;
#pragma unroll
        for (int rr = 0; rr < 2; ++rr) {
            int r = w * 2 + rr;
            float inv = sInv[r];
            float4* rowP = (float4*)(sP + r * 2048);
            float4* gout = (float4*)(attn + ((size_t)bh * L_ + q0 + r) * L_);
#pragma unroll 4
            for (int it = 0; it < 16; ++it) {
                int c = lane + it * 32;
                float4 v = rowP[c];
                v.x *= inv; v.y *= inv; v.z *= inv; v.w *= inv;
                rowP[c] = v;
                gout[c] = v;
            }
        }
    }
    __syncthreads();

    const int g = ty;
    const int s = tx;
    const int qb  = (s >> 4) * 4;
    const int dh4 = (s & 15) * 4;
    float4 a0 = make_float4(0, 0, 0, 0), a1 = a0, a2 = a0, a3 = a0;

    for (int vt = 0; vt < 16; ++vt) {
        const float4* Vg = (const float4*)(V + base + (size_t)vt * 128 * DH_);
#pragma unroll
        for (int it = 0; it < 8; ++it) {
            int idx = it * 256 + tid;
            int k = idx >> 4, dq = idx & 15;
            *(float4*)(sV + k * 68 + dq * 4) = Vg[idx];
        }
        __syncthreads();
#pragma unroll 4
        for (int kk = 0; kk < 32; ++kk) {
            int kl = (g << 5) + kk;
            float4 vv = *(const float4*)(sV + kl * 68 + dh4);
            const float* pcol = sP + (vt * 128 + kl);
            float p0 = pcol[(qb + 0) * 2048];
            float p1 = pcol[(qb + 1) * 2048];
            float p2 = pcol[(qb + 2) * 2048];
            float p3 = pcol[(qb + 3) * 2048];
            a0.x = fmaf(p0, vv.x, a0.x); a0.y = fmaf(p0, vv.y, a0.y);
            a0.z = fmaf(p0, vv.z, a0.z); a0.w = fmaf(p0, vv.w, a0.w);
            a1.x = fmaf(p1, vv.x, a1.x); a1.y = fmaf(p1, vv.y, a1.y);
            a1.z = fmaf(p1, vv.z, a1.z); a1.w = fmaf(p1, vv.w, a1.w);
            a2.x = fmaf(p2, vv.x, a2.x); a2.y = fmaf(p2, vv.y, a2.y);
            a2.z = fmaf(p2, vv.z, a2.z); a2.w = fmaf(p2, vv.w, a2.w);
            a3.x = fmaf(p3, vv.x, a3.x); a3.y = fmaf(p3, vv.y, a3.y);
            a3.z = fmaf(p3, vv.z, a3.z); a3.w = fmaf(p3, vv.w, a3.w);
        }
        __syncthreads();
    }

    *(float4*)(red + g * 1024 + s * 16 + 0)  = a0;
    *(float4*)(red + g * 1024 + s * 16 + 4)  = a1;
    *(float4*)(red + g * 1024 + s * 16 + 8)  = a2;
    *(float4*)(red + g * 1024 + s * 16 + 12) = a3;
    __syncthreads();
    {
        int s2 = tid >> 2, c = tid & 3;
        float4 sum = make_float4(0, 0, 0, 0);
#pragma unroll
        for (int gg = 0; gg < 4; ++gg) {
            const float4 v = *(const float4*)(red + gg * 1024 + s2 * 16 + c * 4);
            sum.x += v.x; sum.y += v.y; sum.z += v.z; sum.w += v.w;
        }
        int q  = ((s2 >> 4) << 2) + c;
        int dh = (s2 & 15) << 2;
        int b = bh >> 4, h = bh & 15;
        int l = q0 + q;
        *(float4*)(ctx + ((size_t)(b * L_ + l)) * D_ + h * DH_ + dh) = sum;
    }
}

// ============================================================================
// host launcher
// ============================================================================
extern "C" void kernel_launch(void* const* d_in, const int* in_sizes, int n_in,
                              void* d_out, int out_size)
{
    const float* src = (const float*)d_in[0];
    const float* Wq  = (const float*)d_in[1];
    const float* bq  = (const float*)d_in[2];
    const float* Wk  = (const float*)d_in[3];
    const float* bk  = (const float*)d_in[4];
    const float* Wv  = (const float*)d_in[5];
    const float* bv  = (const float*)d_in[6];
    const float* Wo  = (const float*)d_in[7];
    const float* bo  = (const float*)d_in[8];
    const float* cw  = (const float*)d_in[9];
    const float* cb  = (const float*)d_in[10];

    float* out      = (float*)d_out;
    float* attn_out = out + OUT_ELEMS;

    float *Qp, *Kp, *Vp, *salp, *ctxp;
    __nv_bfloat16 *Ahi, *Alo, *Whi, *Wlo;
    cudaGetSymbolAddress((void**)&Qp,   g_Q);
    cudaGetSymbolAddress((void**)&Kp,   g_K);
    cudaGetSymbolAddress((void**)&Vp,   g_V);
    cudaGetSymbolAddress((void**)&salp, g_sal);
    cudaGetSymbolAddress((void**)&ctxp, g_ctx);
    cudaGetSymbolAddress((void**)&Ahi,  g_Ahi);
    cudaGetSymbolAddress((void**)&Alo,  g_Alo);
    cudaGetSymbolAddress((void**)&Whi,  g_Whi);
    cudaGetSymbolAddress((void**)&Wlo,  g_Wlo);

    cudaFuncSetAttribute(conv_sal_kernel,
        cudaFuncAttributeMaxDynamicSharedMemorySize, CONV_SMEM);
    cudaFuncSetAttribute(attn_kernel,
        cudaFuncAttributeMaxDynamicSharedMemorySize, ATTN_SMEM);
    cudaFuncSetAttribute(mma_gemm_bf16x3,
        cudaFuncAttributeMaxDynamicSharedMemorySize, GEMM_SMEM);

    // saliency conv
    conv_sal_kernel<<<B_ * 128, 256, CONV_SMEM>>>(src, cw, cb, salp);

    // bf16 hi/lo splits
    const int WN4 = D_ * D_ / 4;
    cvt_split<<<(M_ * D_ / 4 + 255) / 256, 256>>>(src, Ahi, Alo, M_ * D_ / 4);
    cvt_split<<<(WN4 + 255) / 256, 256>>>(Wq, Whi + 0 * (size_t)D_ * D_, Wlo + 0 * (size_t)D_ * D_, WN4);
    cvt_split<<<(WN4 + 255) / 256, 256>>>(Wk, Whi + 1 * (size_t)D_ * D_, Wlo + 1 * (size_t)D_ * D_, WN4);
    cvt_split<<<(WN4 + 255) / 256, 256>>>(Wv, Whi + 2 * (size_t)D_ * D_, Wlo + 2 * (size_t)D_ * D_, WN4);
    cvt_split<<<(WN4 + 255) / 256, 256>>>(Wo, Whi + 3 * (size_t)D_ * D_, Wlo + 3 * (size_t)D_ * D_, WN4);

    // QKV projections on tensor cores (HMMA) -> [b,h,l,dh]
    dim3 ggrid(8, 32);
    mma_gemm_bf16x3<<<ggrid, 256, GEMM_SMEM>>>(Ahi, Alo,
        Whi + 0 * (size_t)D_ * D_, Wlo + 0 * (size_t)D_ * D_, bq, Qp, 1);
    mma_gemm_bf16x3<<<ggrid, 256, GEMM_SMEM>>>(Ahi, Alo,
        Whi + 1 * (size_t)D_ * D_, Wlo + 1 * (size_t)D_ * D_, bk, Kp, 1);
    mma_gemm_bf16x3<<<ggrid, 256, GEMM_SMEM>>>(Ahi, Alo,
        Whi + 2 * (size_t)D_ * D_, Wlo + 2 * (size_t)D_ * D_, bv, Vp, 1);

    // fused attention (writes attn + ctx)
    dim3 agrid(L_ / 16, B_ * H_);
    attn_kernel<<<agrid, 256, ATTN_SMEM>>>(Qp, Kp, Vp, salp, ctxp, attn_out);

    // output projection: split ctx, then tensor GEMM -> d_out
    cvt_split<<<(M_ * D_ / 4 + 255) / 256, 256>>>(ctxp, Ahi, Alo, M_ * D_ / 4);
    mma_gemm_bf16x3<<<ggrid, 256, GEMM_SMEM>>>(Ahi, Alo,
        Whi + 3 * (size_t)D_ * D_, Wlo + 3 * (size_t)D_ * D_, bo, out, 0);
}

// round 6
// speedup vs baseline: 1.4769x; 1.2073x over previous
#include <cuda_runtime.h>
#include <cuda_bf16.h>
#include <cstdint>

#define B_ 2
#define L_ 2048
#define D_ 1024
#define H_ 16
#define DH_ 64
#define M_ (B_*L_)
#define OUT_ELEMS (B_*L_*D_)

// -------- scratch (static device arrays; no cudaMalloc allowed) --------
__device__ float g_sal[B_*H_*L_];
__device__ __nv_bfloat16 g_Ahi[M_*D_];
__device__ __nv_bfloat16 g_Alo[M_*D_];
__device__ __nv_bfloat16 g_Whi[4][D_*D_];
__device__ __nv_bfloat16 g_Wlo[4][D_*D_];
__device__ __nv_bfloat16 g_Qh[B_*H_*L_*DH_];
__device__ __nv_bfloat16 g_Ql[B_*H_*L_*DH_];
__device__ __nv_bfloat16 g_Kh[B_*H_*L_*DH_];
__device__ __nv_bfloat16 g_Kl[B_*H_*L_*DH_];
__device__ __nv_bfloat16 g_Vh[B_*H_*L_*DH_];
__device__ __nv_bfloat16 g_Vl[B_*H_*L_*DH_];

__device__ __forceinline__ uint32_t smem_u32(const void* p) {
    uint32_t a;
    asm("{ .reg .u64 t; cvta.to.shared.u64 t, %1; cvt.u32.u64 %0, t; }"
        : "=r"(a) : "l"(p));
    return a;
}

// -------- fast exp on the FMA pipe --------
__device__ __forceinline__ float fast_exp(float x) {
    x = fminf(fmaxf(x, -80.f), 80.f);
    float y = x * 1.4426950408889634f;
    float t = y + 12582912.0f;
    float n = t - 12582912.0f;
    float f = y - n;
    float p = 1.3333558146428443e-3f;
    p = fmaf(p, f, 9.6181291076284772e-3f);
    p = fmaf(p, f, 5.5504108664821580e-2f);
    p = fmaf(p, f, 2.4022650695910072e-1f);
    p = fmaf(p, f, 6.9314718055994531e-1f);
    p = fmaf(p, f, 1.0f);
    int ni = __float2int_rn(n);
    return __int_as_float(__float_as_int(p) + (ni << 23));
}

// hi/lo bf16 split packed into one u32 (hi at low halfword)
__device__ __forceinline__ uint32_t pack_split(float p) {
    __nv_bfloat16 h = __float2bfloat16(p);
    __nv_bfloat16 l = __float2bfloat16(p - __bfloat162float(h));
    return (uint32_t)reinterpret_cast<uint16_t&>(h)
         | ((uint32_t)reinterpret_cast<uint16_t&>(l) << 16);
}

// ---------------- mma/ldmatrix primitives ----------------
__device__ __forceinline__ void ldm_x4(uint32_t* r, uint32_t addr) {
    asm volatile("ldmatrix.sync.aligned.m8n8.x4.shared.b16 {%0,%1,%2,%3}, [%4];"
        : "=r"(r[0]), "=r"(r[1]), "=r"(r[2]), "=r"(r[3]) : "r"(addr));
}
__device__ __forceinline__ void ldm_x2(uint32_t* r, uint32_t addr) {
    asm volatile("ldmatrix.sync.aligned.m8n8.x2.shared.b16 {%0,%1}, [%2];"
        : "=r"(r[0]), "=r"(r[1]) : "r"(addr));
}
__device__ __forceinline__ void ldm_x2_t(uint32_t* r, uint32_t addr) {
    asm volatile("ldmatrix.sync.aligned.m8n8.x2.trans.shared.b16 {%0,%1}, [%2];"
        : "=r"(r[0]), "=r"(r[1]) : "r"(addr));
}
__device__ __forceinline__ void mma16816(float* c, const uint32_t* a, const uint32_t* b) {
    asm volatile(
        "mma.sync.aligned.m16n8k16.row.col.f32.bf16.bf16.f32 "
        "{%0,%1,%2,%3}, {%4,%5,%6,%7}, {%8,%9}, {%0,%1,%2,%3};"
        : "+f"(c[0]), "+f"(c[1]), "+f"(c[2]), "+f"(c[3])
        : "r"(a[0]), "r"(a[1]), "r"(a[2]), "r"(a[3]), "r"(b[0]), "r"(b[1]));
}

// ============================================================================
// fp32 -> bf16 hi/lo split (vectorized)
// ============================================================================
__global__ void __launch_bounds__(256) cvt_split(
    const float* __restrict__ x, __nv_bfloat16* __restrict__ hi,
    __nv_bfloat16* __restrict__ lo, int n4)
{
    int i = blockIdx.x * blockDim.x + threadIdx.x;
    if (i >= n4) return;
    float4 v = ((const float4*)x)[i];
    __nv_bfloat16 h0 = __float2bfloat16(v.x);
    __nv_bfloat16 h1 = __float2bfloat16(v.y);
    __nv_bfloat16 h2 = __float2bfloat16(v.z);
    __nv_bfloat16 h3 = __float2bfloat16(v.w);
    __nv_bfloat162* hp = (__nv_bfloat162*)hi;
    __nv_bfloat162* lp = (__nv_bfloat162*)lo;
    hp[2 * i]     = __nv_bfloat162(h0, h1);
    hp[2 * i + 1] = __nv_bfloat162(h2, h3);
    lp[2 * i]     = __nv_bfloat162(__float2bfloat16(v.x - __bfloat162float(h0)),
                                   __float2bfloat16(v.y - __bfloat162float(h1)));
    lp[2 * i + 1] = __nv_bfloat162(__float2bfloat16(v.z - __bfloat162float(h2)),
                                   __float2bfloat16(v.w - __bfloat162float(h3)));
}

// ============================================================================
// mma.sync bf16x3 GEMM: C[m,n] = sum_k A[m,k]*W[n,k] + bias[n]
// headed=0: fp32 C [m][n].  headed=1: write bf16 hi/lo to Ch/Cl in
// [b,h,l,dh] headed layout (for attention consumption).
// ============================================================================
#define TSTRIDE 40
#define GEMM_SMEM (4 * 128 * TSTRIDE * 2)

__global__ void __launch_bounds__(256) mma_gemm_bf16x3(
    const __nv_bfloat16* __restrict__ Ah, const __nv_bfloat16* __restrict__ Al,
    const __nv_bfloat16* __restrict__ Bh, const __nv_bfloat16* __restrict__ Bl,
    const float* __restrict__ bias, float* __restrict__ C,
    __nv_bfloat16* __restrict__ Ch, __nv_bfloat16* __restrict__ Cl, int headed)
{
    extern __shared__ __align__(128) __nv_bfloat16 smx[];
    __nv_bfloat16* sAh = smx;
    __nv_bfloat16* sAl = smx + 128 * TSTRIDE;
    __nv_bfloat16* sBh = smx + 2 * 128 * TSTRIDE;
    __nv_bfloat16* sBl = smx + 3 * 128 * TSTRIDE;

    const int tid = threadIdx.x;
    const int wid = tid >> 5;
    const int lane = tid & 31;
    const int wm = (wid & 1) * 64;
    const int wn = (wid >> 1) * 32;
    const int m0 = blockIdx.y * 128;
    const int n0 = blockIdx.x * 128;

    float c[4][4][4];
#pragma unroll
    for (int i = 0; i < 4; ++i)
#pragma unroll
        for (int j = 0; j < 4; ++j)
#pragma unroll
            for (int r = 0; r < 4; ++r) c[i][j][r] = 0.f;

    const uint32_t aBase = smem_u32(sAh);
    const int arow = lane & 15, acol = (lane >> 4) << 3;
    const int brow = lane & 7,  bcol = ((lane >> 3) & 1) << 3;

    for (int k0 = 0; k0 < 1024; k0 += 32) {
#pragma unroll
        for (int t = 0; t < 2; ++t) {
            int idx = t * 256 + tid;
            int row = idx >> 2, sub = idx & 3;
            size_t ga = (size_t)(m0 + row) * D_ + k0 + sub * 8;
            size_t gb = (size_t)(n0 + row) * D_ + k0 + sub * 8;
            int so = row * TSTRIDE + sub * 8;
            *(uint4*)(sAh + so) = *(const uint4*)(Ah + ga);
            *(uint4*)(sAl + so) = *(const uint4*)(Al + ga);
            *(uint4*)(sBh + so) = *(const uint4*)(Bh + gb);
            *(uint4*)(sBl + so) = *(const uint4*)(Bl + gb);
        }
        __syncthreads();

#pragma unroll
        for (int ks = 0; ks < 2; ++ks) {
            const int kk = ks * 16;
            uint32_t ah[4][4], al[4][4];
#pragma unroll
            for (int mt = 0; mt < 4; ++mt) {
                uint32_t off = (uint32_t)((wm + mt * 16 + arow) * TSTRIDE + kk + acol) * 2;
                ldm_x4(ah[mt], aBase + off);
                ldm_x4(al[mt], aBase + (uint32_t)(128 * TSTRIDE * 2) + off);
            }
#pragma unroll
            for (int nt = 0; nt < 4; ++nt) {
                uint32_t boff = (uint32_t)((wn + nt * 8 + brow) * TSTRIDE + kk + bcol) * 2;
                uint32_t bh[2], bl[2];
                ldm_x2(bh, aBase + (uint32_t)(2 * 128 * TSTRIDE * 2) + boff);
                ldm_x2(bl, aBase + (uint32_t)(3 * 128 * TSTRIDE * 2) + boff);
#pragma unroll
                for (int mt = 0; mt < 4; ++mt) {
                    mma16816(c[mt][nt], ah[mt], bh);
                    mma16816(c[mt][nt], ah[mt], bl);
                    mma16816(c[mt][nt], al[mt], bh);
                }
            }
        }
        __syncthreads();
    }

    const int rl = lane >> 2;
    const int cl = (lane & 3) * 2;
#pragma unroll
    for (int mt = 0; mt < 4; ++mt) {
#pragma unroll
        for (int half = 0; half < 2; ++half) {
            int m = m0 + wm + mt * 16 + rl + half * 8;
            int b = m >> 11, l = m & 2047;
#pragma unroll
            for (int nt = 0; nt < 4; ++nt) {
                int n = n0 + wn + nt * 8 + cl;
                float v0 = c[mt][nt][half * 2 + 0] + bias[n];
                float v1 = c[mt][nt][half * 2 + 1] + bias[n + 1];
                if (!headed) {
                    *(float2*)(C + (size_t)m * D_ + n) = make_float2(v0, v1);
                } else {
                    int h = n >> 6, dh = n & 63;
                    size_t off = (size_t)(((b << 4) + h) * 2048 + l) * 64 + dh;
                    __nv_bfloat16 h0 = __float2bfloat16(v0);
                    __nv_bfloat16 h1 = __float2bfloat16(v1);
                    *(__nv_bfloat162*)(Ch + off) = __nv_bfloat162(h0, h1);
                    *(__nv_bfloat162*)(Cl + off) = __nv_bfloat162(
                        __float2bfloat16(v0 - __bfloat162float(h0)),
                        __float2bfloat16(v1 - __bfloat162float(h1)));
                }
            }
        }
    }
}

// ============================================================================
// Saliency Conv1d(D->H, k=3, pad=1): sal[b,h,l]
// ============================================================================
#define CONV_SMEM (18 * 1028 * 4)
__global__ void __launch_bounds__(256) conv_sal_kernel(
    const float* __restrict__ src, const float* __restrict__ cw,
    const float* __restrict__ cb, float* __restrict__ sal)
{
    extern __shared__ float ss[];
    const int bid = blockIdx.x;
    const int b = bid >> 7, lt = bid & 127;
    const int l0 = lt * 16;
    const int tid = threadIdx.x;

#pragma unroll
    for (int it = 0; it < 18; ++it) {
        int idx = it * 256 + tid;
        int row = idx >> 8;
        int c4 = idx & 255;
        int gl = l0 + row - 1;
        float4 v = make_float4(0.f, 0.f, 0.f, 0.f);
        if (gl >= 0 && gl < L_)
            v = *(const float4*)(src + ((size_t)b * L_ + gl) * D_ + c4 * 4);
        *(float4*)(ss + row * 1028 + c4 * 4) = v;
    }
    __syncthreads();

    const int h = tid >> 4, li = tid & 15;
    const float* wp = cw + (size_t)h * D_ * 3;
    float acc = 0.f;
#pragma unroll 4
    for (int d = 0; d < D_; ++d) {
        float w0 = wp[d * 3 + 0], w1 = wp[d * 3 + 1], w2 = wp[d * 3 + 2];
        acc = fmaf(ss[(li + 0) * 1028 + d], w0, acc);
        acc = fmaf(ss[(li + 1) * 1028 + d], w1, acc);
        acc = fmaf(ss[(li + 2) * 1028 + d], w2, acc);
    }
    sal[(size_t)(b * H_ + h) * L_ + l0 + li] = acc + cb[h];
}

// ============================================================================
// Fused tensor-core attention per block (bh, 16 q-rows):
//  S = QK^T/8 + sal (bf16x3 HMMA) -> exp -> rowsum -> normalize
//  -> attn write + in-place pack P to interleaved bf16 hi/lo
//  -> ctx = P'(Vh'+Vl') (HMMA, duplicated V rows) -> ctx written split bf16
// SMEM (bytes): sP[16][2052]f32 @0 (131328), KV region @131328 (73728),
//  Q @205056 (4608), sal @209664 (8192), sum @217856, inv @218880
// ============================================================================
#define P_PITCH 2052
#define ATTN_SMEM 218944

__global__ void __launch_bounds__(256) attn_kernel(
    const __nv_bfloat16* __restrict__ Qh, const __nv_bfloat16* __restrict__ Ql,
    const __nv_bfloat16* __restrict__ Kh, const __nv_bfloat16* __restrict__ Kl,
    const __nv_bfloat16* __restrict__ Vh, const __nv_bfloat16* __restrict__ Vl,
    const float* __restrict__ sal,
    __nv_bfloat16* __restrict__ ctxh, __nv_bfloat16* __restrict__ ctxl,
    float* __restrict__ attn)
{
    extern __shared__ __align__(128) char smem[];
    float* sP  = (float*)smem;
    __nv_bfloat16* sKh = (__nv_bfloat16*)(smem + 131328);   // [128][72]
    __nv_bfloat16* sKl = sKh + 128 * 72;
    __nv_bfloat16* sVh = (__nv_bfloat16*)(smem + 131328);   // [256][72] (phase 2)
    __nv_bfloat16* sVl = sVh + 256 * 72;
    __nv_bfloat16* sQh = (__nv_bfloat16*)(smem + 205056);   // [16][72]
    __nv_bfloat16* sQl = sQh + 16 * 72;
    float* sSal = (float*)(smem + 209664);
    float* sSum = (float*)(smem + 217856);
    float* sInv = (float*)(smem + 218880);

    const int tid = threadIdx.x;
    const int wid = tid >> 5;
    const int lane = tid & 31;
    const int q0 = blockIdx.x * 16;
    const int bh = blockIdx.y;
    const size_t base = (size_t)bh * (L_ * DH_);

    // stage sal row (2048 f32) and Q tile (16x64 bf16 hi+lo)
    {
        const float4* gs = (const float4*)(sal + (size_t)bh * L_);
        ((float4*)sSal)[tid] = gs[tid];
        ((float4*)sSal)[256 + tid] = gs[256 + tid];
        int idx = tid & 127;
        int r = idx >> 3, s = idx & 7;
        const uint4* gq = (const uint4*)((tid < 128 ? Qh : Ql) + base + (size_t)q0 * DH_);
        __nv_bfloat16* dq = (tid < 128 ? sQh : sQl);
        *(uint4*)(dq + r * 72 + s * 8) = gq[idx];
    }
    __syncthreads();

    const uint32_t sPb  = smem_u32(sP);
    const uint32_t sKhb = smem_u32(sKh);
    const uint32_t sKlb = smem_u32(sKl);
    const uint32_t sQhb = smem_u32(sQh);
    const uint32_t sQlb = smem_u32(sQl);

    // preload Q fragments (m16 x k64 = 4 k-steps, hi + lo)
    const int arow = lane & 15, acol = (lane >> 4) << 3;
    uint32_t fQh[4][4], fQl[4][4];
#pragma unroll
    for (int ks = 0; ks < 4; ++ks) {
        uint32_t off = (uint32_t)(arow * 72 + ks * 16 + acol) * 2;
        ldm_x4(fQh[ks], sQhb + off);
        ldm_x4(fQl[ks], sQlb + off);
    }

    // ---- Phase 1: S = QK^T/8 + sal ----
    const int brow = lane & 7, bcol = ((lane >> 3) & 1) << 3;
    for (int kt = 0; kt < 16; ++kt) {
        const uint4* gKh4 = (const uint4*)(Kh + base + (size_t)kt * 128 * DH_);
        const uint4* gKl4 = (const uint4*)(Kl + base + (size_t)kt * 128 * DH_);
#pragma unroll
        for (int t = 0; t < 4; ++t) {
            int idx = t * 256 + tid;
            int r = idx >> 3, s = idx & 7;
            *(uint4*)(sKh + r * 72 + s * 8) = gKh4[idx];
            *(uint4*)(sKl + r * 72 + s * 8) = gKl4[idx];
        }
        __syncthreads();

#pragma unroll
        for (int nn = 0; nn < 2; ++nn) {
            const int n8 = wid * 2 + nn;
            float c[4] = {0.f, 0.f, 0.f, 0.f};
            uint32_t bo = (uint32_t)((n8 * 8 + brow) * 72 + bcol) * 2;
#pragma unroll
            for (int ks = 0; ks < 4; ++ks) {
                uint32_t bhf[2], blf[2];
                ldm_x2(bhf, sKhb + bo + ks * 32);
                ldm_x2(blf, sKlb + bo + ks * 32);
                mma16816(c, fQh[ks], bhf);
                mma16816(c, fQl[ks], bhf);
                mma16816(c, fQh[ks], blf);
            }
            int col = kt * 128 + n8 * 8 + (lane & 3) * 2;
            int row = lane >> 2;
            float s0 = sSal[col], s1 = sSal[col + 1];
            *(float2*)(sP + row * P_PITCH + col) =
                make_float2(fmaf(c[0], 0.125f, s0), fmaf(c[1], 0.125f, s1));
            *(float2*)(sP + (row + 8) * P_PITCH + col) =
                make_float2(fmaf(c[2], 0.125f, s0), fmaf(c[3], 0.125f, s1));
        }
        __syncthreads();
    }

    // ---- softmax: exp + rowsum ----
    {
        int r = tid >> 4, seg = tid & 15;
        float* rowp = sP + r * P_PITCH;
        float psum = 0.f;
#pragma unroll 4
        for (int j = 0; j < 128; ++j) {
            int col = seg + (j << 4);
            float e = fast_exp(rowp[col]);
            rowp[col] = e;
            psum += e;
        }
        sSum[r * 16 + seg] = psum;
    }
    __syncthreads();
    if (tid < 16) {
        float s = 0.f;
#pragma unroll
        for (int i = 0; i < 16; ++i) s += sSum[tid * 16 + i];
        sInv[tid] = 1.f / s;
    }
    __syncthreads();

    // ---- normalize + attn write + in-place pack to interleaved bf16 hi/lo ----
    {
        int w = tid >> 5, ln = tid & 31;
#pragma unroll
        for (int rr = 0; rr < 2; ++rr) {
            int r = w * 2 + rr;
            float inv = sInv[r];
            float* rowP = sP + r * P_PITCH;
            float4* gout = (float4*)(attn + ((size_t)bh * L_ + q0 + r) * L_);
#pragma unroll 4
            for (int it = 0; it < 16; ++it) {
                int c4 = ln + it * 32;
                float4 v = ((float4*)rowP)[c4];
                v.x *= inv; v.y *= inv; v.z *= inv; v.w *= inv;
                gout[c4] = v;
                uint4 pk;
                pk.x = pack_split(v.x); pk.y = pack_split(v.y);
                pk.z = pack_split(v.z); pk.w = pack_split(v.w);
                ((uint4*)rowP)[c4] = pk;
            }
        }
    }
    __syncthreads();

    // ---- Phase 2: ctx = P' * (Vh' + Vl'), V rows duplicated ----
    const uint32_t sVhb = smem_u32(sVh);
    const uint32_t sVlb = smem_u32(sVl);
    float cc[4] = {0.f, 0.f, 0.f, 0.f};
    const int n8 = wid;
    for (int lt = 0; lt < 16; ++lt) {
        const uint4* gVh4 = (const uint4*)(Vh + base + (size_t)lt * 128 * DH_);
        const uint4* gVl4 = (const uint4*)(Vl + base + (size_t)lt * 128 * DH_);
#pragma unroll
        for (int t = 0; t < 4; ++t) {
            int idx = t * 256 + tid;
            int r = idx >> 3, s = idx & 7;
            uint4 vh = gVh4[idx], vl = gVl4[idx];
            *(uint4*)(sVh + (2 * r) * 72 + s * 8) = vh;
            *(uint4*)(sVh + (2 * r + 1) * 72 + s * 8) = vh;
            *(uint4*)(sVl + (2 * r) * 72 + s * 8) = vl;
            *(uint4*)(sVl + (2 * r + 1) * 72 + s * 8) = vl;
        }
        __syncthreads();

#pragma unroll 4
        for (int ks = 0; ks < 16; ++ks) {
            int kp = lt * 256 + ks * 16;        // bf16 element index in P'
            uint32_t aaddr = sPb + (uint32_t)(arow * (P_PITCH * 4))
                           + (uint32_t)(kp + acol) * 2;
            uint32_t fA[4];
            ldm_x4(fA, aaddr);
            uint32_t bo = (uint32_t)((ks * 16 + (lane & 15)) * 72 + n8 * 8) * 2;
            uint32_t fBh[2], fBl[2];
            ldm_x2_t(fBh, sVhb + bo);
            ldm_x2_t(fBl, sVlb + bo);
            mma16816(cc, fA, fBh);
            mma16816(cc, fA, fBl);
        }
        __syncthreads();
    }

    // ---- ctx epilogue: write split bf16 into Wo-GEMM A operand ----
    {
        int row = lane >> 2;
        int colp = (lane & 3) * 2;
        int b = bh >> 4, h = bh & 15;
        int n = h * 64 + n8 * 8 + colp;
#pragma unroll
        for (int half = 0; half < 2; ++half) {
            int m = b * 2048 + q0 + row + half * 8;
            float v0 = cc[half * 2 + 0], v1 = cc[half * 2 + 1];
            __nv_bfloat16 h0 = __float2bfloat16(v0);
            __nv_bfloat16 h1 = __float2bfloat16(v1);
            *(__nv_bfloat162*)(ctxh + (size_t)m * D_ + n) = __nv_bfloat162(h0, h1);
            *(__nv_bfloat162*)(ctxl + (size_t)m * D_ + n) = __nv_bfloat162(
                __float2bfloat16(v0 - __bfloat162float(h0)),
                __float2bfloat16(v1 - __bfloat162float(h1)));
        }
    }
}

// ============================================================================
// host launcher
// ============================================================================
extern "C" void kernel_launch(void* const* d_in, const int* in_sizes, int n_in,
                              void* d_out, int out_size)
{
    const float* src = (const float*)d_in[0];
    const float* Wq  = (const float*)d_in[1];
    const float* bq  = (const float*)d_in[2];
    const float* Wk  = (const float*)d_in[3];
    const float* bk  = (const float*)d_in[4];
    const float* Wv  = (const float*)d_in[5];
    const float* bv  = (const float*)d_in[6];
    const float* Wo  = (const float*)d_in[7];
    const float* bo  = (const float*)d_in[8];
    const float* cw  = (const float*)d_in[9];
    const float* cb  = (const float*)d_in[10];

    float* out      = (float*)d_out;
    float* attn_out = out + OUT_ELEMS;

    float* salp;
    __nv_bfloat16 *Ahi, *Alo, *Whi, *Wlo;
    __nv_bfloat16 *Qh, *Ql, *Kh, *Kl, *Vh, *Vl;
    cudaGetSymbolAddress((void**)&salp, g_sal);
    cudaGetSymbolAddress((void**)&Ahi,  g_Ahi);
    cudaGetSymbolAddress((void**)&Alo,  g_Alo);
    cudaGetSymbolAddress((void**)&Whi,  g_Whi);
    cudaGetSymbolAddress((void**)&Wlo,  g_Wlo);
    cudaGetSymbolAddress((void**)&Qh,   g_Qh);
    cudaGetSymbolAddress((void**)&Ql,   g_Ql);
    cudaGetSymbolAddress((void**)&Kh,   g_Kh);
    cudaGetSymbolAddress((void**)&Kl,   g_Kl);
    cudaGetSymbolAddress((void**)&Vh,   g_Vh);
    cudaGetSymbolAddress((void**)&Vl,   g_Vl);

    cudaFuncSetAttribute(conv_sal_kernel,
        cudaFuncAttributeMaxDynamicSharedMemorySize, CONV_SMEM);
    cudaFuncSetAttribute(attn_kernel,
        cudaFuncAttributeMaxDynamicSharedMemorySize, ATTN_SMEM);
    cudaFuncSetAttribute(mma_gemm_bf16x3,
        cudaFuncAttributeMaxDynamicSharedMemorySize, GEMM_SMEM);

    // saliency conv
    conv_sal_kernel<<<B_ * 128, 256, CONV_SMEM>>>(src, cw, cb, salp);

    // bf16 hi/lo splits of src and weights
    const int WN4 = D_ * D_ / 4;
    cvt_split<<<(M_ * D_ / 4 + 255) / 256, 256>>>(src, Ahi, Alo, M_ * D_ / 4);
    cvt_split<<<(WN4 + 255) / 256, 256>>>(Wq, Whi + 0 * (size_t)D_ * D_, Wlo + 0 * (size_t)D_ * D_, WN4);
    cvt_split<<<(WN4 + 255) / 256, 256>>>(Wk, Whi + 1 * (size_t)D_ * D_, Wlo + 1 * (size_t)D_ * D_, WN4);
    cvt_split<<<(WN4 + 255) / 256, 256>>>(Wv, Whi + 2 * (size_t)D_ * D_, Wlo + 2 * (size_t)D_ * D_, WN4);
    cvt_split<<<(WN4 + 255) / 256, 256>>>(Wo, Whi + 3 * (size_t)D_ * D_, Wlo + 3 * (size_t)D_ * D_, WN4);

    // QKV projections (HMMA) -> split bf16 headed layout
    dim3 ggrid(8, 32);
    mma_gemm_bf16x3<<<ggrid, 256, GEMM_SMEM>>>(Ahi, Alo,
        Whi + 0 * (size_t)D_ * D_, Wlo + 0 * (size_t)D_ * D_, bq, nullptr, Qh, Ql, 1);
    mma_gemm_bf16x3<<<ggrid, 256, GEMM_SMEM>>>(Ahi, Alo,
        Whi + 1 * (size_t)D_ * D_, Wlo + 1 * (size_t)D_ * D_, bk, nullptr, Kh, Kl, 1);
    mma_gemm_bf16x3<<<ggrid, 256, GEMM_SMEM>>>(Ahi, Alo,
        Whi + 2 * (size_t)D_ * D_, Wlo + 2 * (size_t)D_ * D_, bv, nullptr, Vh, Vl, 1);

    // fused tensor-core attention (writes attn + ctx split into Ahi/Alo)
    dim3 agrid(L_ / 16, B_ * H_);
    attn_kernel<<<agrid, 256, ATTN_SMEM>>>(Qh, Ql, Kh, Kl, Vh, Vl, salp,
                                           Ahi, Alo, attn_out);

    // output projection (reads ctx split from Ahi/Alo) -> d_out
    mma_gemm_bf16x3<<<ggrid, 256, GEMM_SMEM>>>(Ahi, Alo,
        Whi + 3 * (size_t)D_ * D_, Wlo + 3 * (size_t)D_ * D_, bo, out, nullptr, nullptr, 0);
}

// round 7
// speedup vs baseline: 2.0635x; 1.3972x over previous
#include <cuda_runtime.h>
#include <cuda_bf16.h>
#include <cstdint>

#define B_ 2
#define L_ 2048
#define D_ 1024
#define H_ 16
#define DH_ 64
#define M_ (B_*L_)
#define OUT_ELEMS (B_*L_*D_)

// -------- scratch (static device arrays; no cudaMalloc allowed) --------
__device__ float g_sal[B_*H_*L_];
__device__ __nv_bfloat16 g_Ahi[M_*D_];
__device__ __nv_bfloat16 g_Alo[M_*D_];
__device__ __nv_bfloat16 g_Whi[4][D_*D_];
__device__ __nv_bfloat16 g_Wlo[4][D_*D_];
__device__ __nv_bfloat16 g_Qh[B_*H_*L_*DH_];
__device__ __nv_bfloat16 g_Ql[B_*H_*L_*DH_];
__device__ __nv_bfloat16 g_Kh[B_*H_*L_*DH_];
__device__ __nv_bfloat16 g_Kl[B_*H_*L_*DH_];
__device__ __nv_bfloat16 g_Vh[B_*H_*L_*DH_];
__device__ __nv_bfloat16 g_Vl[B_*H_*L_*DH_];

__device__ __forceinline__ uint32_t smem_u32(const void* p) {
    uint32_t a;
    asm("{ .reg .u64 t; cvta.to.shared.u64 t, %1; cvt.u32.u64 %0, t; }"
        : "=r"(a) : "l"(p));
    return a;
}

// -------- cp.async helpers --------
#define CP_ASYNC16(dst, src) \
    asm volatile("cp.async.cg.shared.global [%0], [%1], 16;" \
        :: "r"(dst), "l"(src))
#define CP_COMMIT() asm volatile("cp.async.commit_group;")
#define CP_WAIT1()  asm volatile("cp.async.wait_group 1;")
#define CP_WAIT0()  asm volatile("cp.async.wait_group 0;")

// -------- fast exp on the FMA pipe --------
__device__ __forceinline__ float fast_exp(float x) {
    x = fminf(fmaxf(x, -80.f), 80.f);
    float y = x * 1.4426950408889634f;
    float t = y + 12582912.0f;
    float n = t - 12582912.0f;
    float f = y - n;
    float p = 1.3333558146428443e-3f;
    p = fmaf(p, f, 9.6181291076284772e-3f);
    p = fmaf(p, f, 5.5504108664821580e-2f);
    p = fmaf(p, f, 2.4022650695910072e-1f);
    p = fmaf(p, f, 6.9314718055994531e-1f);
    p = fmaf(p, f, 1.0f);
    int ni = __float2int_rn(n);
    return __int_as_float(__float_as_int(p) + (ni << 23));
}

// ---------------- mma/ldmatrix primitives ----------------
__device__ __forceinline__ void ldm_x4(uint32_t* r, uint32_t addr) {
    asm volatile("ldmatrix.sync.aligned.m8n8.x4.shared.b16 {%0,%1,%2,%3}, [%4];"
        : "=r"(r[0]), "=r"(r[1]), "=r"(r[2]), "=r"(r[3]) : "r"(addr));
}
__device__ __forceinline__ void ldm_x2(uint32_t* r, uint32_t addr) {
    asm volatile("ldmatrix.sync.aligned.m8n8.x2.shared.b16 {%0,%1}, [%2];"
        : "=r"(r[0]), "=r"(r[1]) : "r"(addr));
}
__device__ __forceinline__ void ldm_x2_t(uint32_t* r, uint32_t addr) {
    asm volatile("ldmatrix.sync.aligned.m8n8.x2.trans.shared.b16 {%0,%1}, [%2];"
        : "=r"(r[0]), "=r"(r[1]) : "r"(addr));
}
__device__ __forceinline__ void mma16816(float* c, const uint32_t* a, const uint32_t* b) {
    asm volatile(
        "mma.sync.aligned.m16n8k16.row.col.f32.bf16.bf16.f32 "
        "{%0,%1,%2,%3}, {%4,%5,%6,%7}, {%8,%9}, {%0,%1,%2,%3};"
        : "+f"(c[0]), "+f"(c[1]), "+f"(c[2]), "+f"(c[3])
        : "r"(a[0]), "r"(a[1]), "r"(a[2]), "r"(a[3]), "r"(b[0]), "r"(b[1]));
}

// ============================================================================
// fp32 -> bf16 hi/lo split (vectorized)
// ============================================================================
__global__ void __launch_bounds__(256) cvt_split(
    const float* __restrict__ x, __nv_bfloat16* __restrict__ hi,
    __nv_bfloat16* __restrict__ lo, int n4)
{
    int i = blockIdx.x * blockDim.x + threadIdx.x;
    if (i >= n4) return;
    float4 v = ((const float4*)x)[i];
    __nv_bfloat16 h0 = __float2bfloat16(v.x);
    __nv_bfloat16 h1 = __float2bfloat16(v.y);
    __nv_bfloat16 h2 = __float2bfloat16(v.z);
    __nv_bfloat16 h3 = __float2bfloat16(v.w);
    __nv_bfloat162* hp = (__nv_bfloat162*)hi;
    __nv_bfloat162* lp = (__nv_bfloat162*)lo;
    hp[2 * i]     = __nv_bfloat162(h0, h1);
    hp[2 * i + 1] = __nv_bfloat162(h2, h3);
    lp[2 * i]     = __nv_bfloat162(__float2bfloat16(v.x - __bfloat162float(h0)),
                                   __float2bfloat16(v.y - __bfloat162float(h1)));
    lp[2 * i + 1] = __nv_bfloat162(__float2bfloat16(v.z - __bfloat162float(h2)),
                                   __float2bfloat16(v.w - __bfloat162float(h3)));
}

// ============================================================================
// mma.sync bf16x3 GEMM with cp.async double-buffered staging.
// C[m,n] = sum_k A[m,k]*W[n,k] + bias[n];  C = AhBh + AhBl + AlBh.
// 128x128 tile, 8 warps (64x32), BK=32. 2 stages x 4 tiles x [128][40] bf16.
// ============================================================================
#define TSTRIDE 40
#define GSTAGE 40960                  // bytes per stage (4 * 128*40*2)
#define GEMM_SMEM (2 * GSTAGE)

__global__ void __launch_bounds__(256) mma_gemm_bf16x3(
    const __nv_bfloat16* __restrict__ Ah, const __nv_bfloat16* __restrict__ Al,
    const __nv_bfloat16* __restrict__ Bh, const __nv_bfloat16* __restrict__ Bl,
    const float* __restrict__ bias, float* __restrict__ C,
    __nv_bfloat16* __restrict__ Ch, __nv_bfloat16* __restrict__ Cl, int headed)
{
    extern __shared__ __align__(128) char smg[];
    const uint32_t smb = smem_u32(smg);

    const int tid = threadIdx.x;
    const int wid = tid >> 5;
    const int lane = tid & 31;
    const int wm = (wid & 1) * 64;
    const int wn = (wid >> 1) * 32;
    const int m0 = blockIdx.y * 128;
    const int n0 = blockIdx.x * 128;

    float c[4][4][4];
#pragma unroll
    for (int i = 0; i < 4; ++i)
#pragma unroll
        for (int j = 0; j < 4; ++j)
#pragma unroll
            for (int r = 0; r < 4; ++r) c[i][j][r] = 0.f;

    auto issue = [&](int i, int st) {
        const int k0 = i * 32;
        const uint32_t sb = smb + st * GSTAGE;
#pragma unroll
        for (int t = 0; t < 2; ++t) {
            int idx = t * 256 + tid;
            int row = idx >> 2, sub = idx & 3;
            uint32_t off = (uint32_t)(row * TSTRIDE + sub * 8) * 2;
            size_t ga = (size_t)(m0 + row) * D_ + k0 + sub * 8;
            size_t gb = (size_t)(n0 + row) * D_ + k0 + sub * 8;
            CP_ASYNC16(sb + off,         Ah + ga);
            CP_ASYNC16(sb + 10240 + off, Al + ga);
            CP_ASYNC16(sb + 20480 + off, Bh + gb);
            CP_ASYNC16(sb + 30720 + off, Bl + gb);
        }
    };

    const int arow = lane & 15, acol = (lane >> 4) << 3;
    const int brow = lane & 7,  bcol = ((lane >> 3) & 1) << 3;

    issue(0, 0); CP_COMMIT();
    issue(1, 1); CP_COMMIT();

    for (int i = 0; i < 32; ++i) {
        if (i < 31) CP_WAIT1(); else CP_WAIT0();
        __syncthreads();
        const uint32_t aB = smb + (i & 1) * GSTAGE;

#pragma unroll
        for (int ks = 0; ks < 2; ++ks) {
            const int kk = ks * 16;
            uint32_t ah[4][4], al[4][4];
#pragma unroll
            for (int mt = 0; mt < 4; ++mt) {
                uint32_t off = (uint32_t)((wm + mt * 16 + arow) * TSTRIDE + kk + acol) * 2;
                ldm_x4(ah[mt], aB + off);
                ldm_x4(al[mt], aB + 10240 + off);
            }
#pragma unroll
            for (int nt = 0; nt < 4; ++nt) {
                uint32_t boff = (uint32_t)((wn + nt * 8 + brow) * TSTRIDE + kk + bcol) * 2;
                uint32_t bh[2], bl[2];
                ldm_x2(bh, aB + 20480 + boff);
                ldm_x2(bl, aB + 30720 + boff);
#pragma unroll
                for (int mt = 0; mt < 4; ++mt) {
                    mma16816(c[mt][nt], ah[mt], bh);
                    mma16816(c[mt][nt], ah[mt], bl);
                    mma16816(c[mt][nt], al[mt], bh);
                }
            }
        }
        __syncthreads();
        if (i + 2 < 32) { issue(i + 2, i & 1); CP_COMMIT(); }
    }

    const int rl = lane >> 2;
    const int cl = (lane & 3) * 2;
#pragma unroll
    for (int mt = 0; mt < 4; ++mt) {
#pragma unroll
        for (int half = 0; half < 2; ++half) {
            int m = m0 + wm + mt * 16 + rl + half * 8;
            int b = m >> 11, l = m & 2047;
#pragma unroll
            for (int nt = 0; nt < 4; ++nt) {
                int n = n0 + wn + nt * 8 + cl;
                float v0 = c[mt][nt][half * 2 + 0] + bias[n];
                float v1 = c[mt][nt][half * 2 + 1] + bias[n + 1];
                if (!headed) {
                    *(float2*)(C + (size_t)m * D_ + n) = make_float2(v0, v1);
                } else {
                    int h = n >> 6, dh = n & 63;
                    size_t off = (size_t)(((b << 4) + h) * 2048 + l) * 64 + dh;
                    __nv_bfloat16 h0 = __float2bfloat16(v0);
                    __nv_bfloat16 h1 = __float2bfloat16(v1);
                    *(__nv_bfloat162*)(Ch + off) = __nv_bfloat162(h0, h1);
                    *(__nv_bfloat162*)(Cl + off) = __nv_bfloat162(
                        __float2bfloat16(v0 - __bfloat162float(h0)),
                        __float2bfloat16(v1 - __bfloat162float(h1)));
                }
            }
        }
    }
}

// ============================================================================
// Saliency Conv1d(D->H, k=3, pad=1): sal[b,h,l]
// ============================================================================
#define CONV_SMEM (18 * 1028 * 4)
__global__ void __launch_bounds__(256) conv_sal_kernel(
    const float* __restrict__ src, const float* __restrict__ cw,
    const float* __restrict__ cb, float* __restrict__ sal)
{
    extern __shared__ float ss[];
    const int bid = blockIdx.x;
    const int b = bid >> 7, lt = bid & 127;
    const int l0 = lt * 16;
    const int tid = threadIdx.x;

#pragma unroll
    for (int it = 0; it < 18; ++it) {
        int idx = it * 256 + tid;
        int row = idx >> 8;
        int c4 = idx & 255;
        int gl = l0 + row - 1;
        float4 v = make_float4(0.f, 0.f, 0.f, 0.f);
        if (gl >= 0 && gl < L_)
            v = *(const float4*)(src + ((size_t)b * L_ + gl) * D_ + c4 * 4);
        *(float4*)(ss + row * 1028 + c4 * 4) = v;
    }
    __syncthreads();

    const int h = tid >> 4, li = tid & 15;
    const float* wp = cw + (size_t)h * D_ * 3;
    float acc = 0.f;
#pragma unroll 4
    for (int d = 0; d < D_; ++d) {
        float w0 = wp[d * 3 + 0], w1 = wp[d * 3 + 1], w2 = wp[d * 3 + 2];
        acc = fmaf(ss[(li + 0) * 1028 + d], w0, acc);
        acc = fmaf(ss[(li + 1) * 1028 + d], w1, acc);
        acc = fmaf(ss[(li + 2) * 1028 + d], w2, acc);
    }
    sal[(size_t)(b * H_ + h) * L_ + l0 + li] = acc + cb[h];
}

// ============================================================================
// Fused tensor-core attention per block (bh, 16 q-rows):
//  Phase1: S = QK^T/8 + sal (bf16x3 HMMA, cp.async double-buffered K),
//          exp fused into MMA epilogue, row-sums in registers.
//  Phase2: per k-tile: normalize + attn write + pack Ph/Pl, then
//          ctx += Ph*Vh + Ph*Vl + Pl*Vh (3-term, cp.async double-buffered V).
// SMEM layout (bytes):
//  sP fp32 16x2052      @ 0        131,328
//  K/V stages (2x36864) @ 131,328  ..205,056  (per stage: hi @0, lo @18,432)
//  Ph tile 16x136 bf16  @ 205,056  4,352
//  Pl tile              @ 209,408  4,352
//  sal fp32 2048        @ 213,760  8,192
//  Q (Qh,Ql 16x72 bf16) @ 221,952  4,608
//  sum 16x8 f32         @ 226,560  512
//  inv 16 f32           @ 227,072  64
// ============================================================================
#define P_PITCH 2052
#define KV_OFF  131328
#define KV_STG  36864
#define PH_OFF  205056
#define PL_OFF  209408
#define SAL_OFF 213760
#define Q_OFF   221952
#define SUM_OFF 226560
#define INV_OFF 227072
#define ATTN_SMEM 227136

__global__ void __launch_bounds__(256) attn_kernel(
    const __nv_bfloat16* __restrict__ Qh, const __nv_bfloat16* __restrict__ Ql,
    const __nv_bfloat16* __restrict__ Kh, const __nv_bfloat16* __restrict__ Kl,
    const __nv_bfloat16* __restrict__ Vh, const __nv_bfloat16* __restrict__ Vl,
    const float* __restrict__ sal,
    __nv_bfloat16* __restrict__ ctxh, __nv_bfloat16* __restrict__ ctxl,
    float* __restrict__ attn)
{
    extern __shared__ __align__(128) char smem[];
    float* sP   = (float*)smem;
    float* sSal = (float*)(smem + SAL_OFF);
    float* sSum = (float*)(smem + SUM_OFF);
    float* sInv = (float*)(smem + INV_OFF);
    const uint32_t smb = smem_u32(smem);

    const int tid = threadIdx.x;
    const int wid = tid >> 5;
    const int lane = tid & 31;
    const int q0 = blockIdx.x * 16;
    const int bh = blockIdx.y;
    const size_t base = (size_t)bh * (L_ * DH_);

    // stage sal row + Q tile
    {
        const float4* gs = (const float4*)(sal + (size_t)bh * L_);
        ((float4*)sSal)[tid] = gs[tid];
        ((float4*)sSal)[256 + tid] = gs[256 + tid];
        int idx = tid & 127;
        int r = idx >> 3, s = idx & 7;
        const uint4* gq = (const uint4*)((tid < 128 ? Qh : Ql) + base + (size_t)q0 * DH_);
        __nv_bfloat16* dq = (__nv_bfloat16*)(smem + Q_OFF) + (tid < 128 ? 0 : 16 * 72);
        *(uint4*)(dq + r * 72 + s * 8) = gq[idx];
    }
    __syncthreads();

    // preload Q fragments (m16 x k64, hi + lo)
    const int arow = lane & 15, acol = (lane >> 4) << 3;
    const int brow = lane & 7,  bcol = ((lane >> 3) & 1) << 3;
    uint32_t fQh[4][4], fQl[4][4];
    {
        const uint32_t qhB = smb + Q_OFF;
        const uint32_t qlB = qhB + 16 * 72 * 2;
#pragma unroll
        for (int ks = 0; ks < 4; ++ks) {
            uint32_t off = (uint32_t)(arow * 72 + ks * 16 + acol) * 2;
            ldm_x4(fQh[ks], qhB + off);
            ldm_x4(fQl[ks], qlB + off);
        }
    }

    auto issueKV = [&](const __nv_bfloat16* gh, const __nv_bfloat16* gl,
                       int t128, int st) {
        const uint32_t sb = smb + KV_OFF + st * KV_STG;
        const __nv_bfloat16* ph = gh + base + (size_t)t128 * 128 * DH_;
        const __nv_bfloat16* pl = gl + base + (size_t)t128 * 128 * DH_;
#pragma unroll
        for (int t = 0; t < 4; ++t) {
            int idx = t * 256 + tid;
            int r = idx >> 3, s = idx & 7;
            uint32_t off = (uint32_t)(r * 72 + s * 8) * 2;
            CP_ASYNC16(sb + off,         ph + (size_t)r * DH_ + s * 8);
            CP_ASYNC16(sb + 18432 + off, pl + (size_t)r * DH_ + s * 8);
        }
    };

    // ---- Phase 1: S = exp(QK^T/8 + sal), partial row sums in registers ----
    issueKV(Kh, Kl, 0, 0); CP_COMMIT();
    issueKV(Kh, Kl, 1, 1); CP_COMMIT();

    float sum_lo = 0.f, sum_hi = 0.f;
    for (int kt = 0; kt < 16; ++kt) {
        if (kt < 15) CP_WAIT1(); else CP_WAIT0();
        __syncthreads();
        const uint32_t kb = smb + KV_OFF + (kt & 1) * KV_STG;

#pragma unroll
        for (int nn = 0; nn < 2; ++nn) {
            const int n8 = wid * 2 + nn;
            float c[4] = {0.f, 0.f, 0.f, 0.f};
            uint32_t bo  = kb + (uint32_t)((n8 * 8 + brow) * 72 + bcol) * 2;
#pragma unroll
            for (int ks = 0; ks < 4; ++ks) {
                uint32_t bhf[2], blf[2];
                ldm_x2(bhf, bo + ks * 32);
                ldm_x2(blf, bo + 18432 + ks * 32);
                mma16816(c, fQh[ks], bhf);
                mma16816(c, fQl[ks], bhf);
                mma16816(c, fQh[ks], blf);
            }
            int col = kt * 128 + n8 * 8 + (lane & 3) * 2;
            float s0 = sSal[col], s1 = sSal[col + 1];
            float e0 = fast_exp(fmaf(c[0], 0.125f, s0));
            float e1 = fast_exp(fmaf(c[1], 0.125f, s1));
            float e2 = fast_exp(fmaf(c[2], 0.125f, s0));
            float e3 = fast_exp(fmaf(c[3], 0.125f, s1));
            int row = lane >> 2;
            *(float2*)(sP + row * P_PITCH + col) = make_float2(e0, e1);
            *(float2*)(sP + (row + 8) * P_PITCH + col) = make_float2(e2, e3);
            sum_lo += e0 + e1;
            sum_hi += e2 + e3;
        }
        __syncthreads();
        if (kt + 2 < 16) { issueKV(Kh, Kl, kt + 2, kt & 1); CP_COMMIT(); }
    }

    // start V pipeline early (K stages fully consumed)
    issueKV(Vh, Vl, 0, 0); CP_COMMIT();
    issueKV(Vh, Vl, 1, 1); CP_COMMIT();

    // ---- row-sum reduction -> sInv ----
    sum_lo += __shfl_xor_sync(0xffffffffu, sum_lo, 1);
    sum_lo += __shfl_xor_sync(0xffffffffu, sum_lo, 2);
    sum_hi += __shfl_xor_sync(0xffffffffu, sum_hi, 1);
    sum_hi += __shfl_xor_sync(0xffffffffu, sum_hi, 2);
    if ((lane & 3) == 0) {
        sSum[(lane >> 2) * 8 + wid] = sum_lo;
        sSum[((lane >> 2) + 8) * 8 + wid] = sum_hi;
    }
    __syncthreads();
    if (tid < 16) {
        float s = 0.f;
#pragma unroll
        for (int j = 0; j < 8; ++j) s += sSum[tid * 8 + j];
        sInv[tid] = 1.f / s;
    }
    __syncthreads();

    // ---- Phase 2: normalize+write attn+pack per tile, 3-term PV ----
    const uint32_t phB = smb + PH_OFF;
    const uint32_t plB = smb + PL_OFF;
    __nv_bfloat16* sPh = (__nv_bfloat16*)(smem + PH_OFF);
    __nv_bfloat16* sPl = (__nv_bfloat16*)(smem + PL_OFF);
    float cc[4] = {0.f, 0.f, 0.f, 0.f};

    for (int lt = 0; lt < 16; ++lt) {
        if (lt < 15) CP_WAIT1(); else CP_WAIT0();
        __syncthreads();

        // convert current 16x128 slice: scale, write attn, pack hi/lo
        {
            int row = tid >> 4;
            float inv = sInv[row];
            const float* rowp = sP + row * P_PITCH + lt * 128;
            float* gout = attn + ((size_t)bh * L_ + q0 + row) * L_ + lt * 128;
            __nv_bfloat16* ph = sPh + row * 136;
            __nv_bfloat16* pl = sPl + row * 136;
#pragma unroll
            for (int p = 0; p < 2; ++p) {
                int cb = (tid & 15) * 4 + p * 64;
                float4 v = *(const float4*)(rowp + cb);
                v.x *= inv; v.y *= inv; v.z *= inv; v.w *= inv;
                *(float4*)(gout + cb) = v;
                __nv_bfloat16 h0 = __float2bfloat16(v.x);
                __nv_bfloat16 h1 = __float2bfloat16(v.y);
                __nv_bfloat16 h2 = __float2bfloat16(v.z);
                __nv_bfloat16 h3 = __float2bfloat16(v.w);
                *(__nv_bfloat162*)(ph + cb)     = __nv_bfloat162(h0, h1);
                *(__nv_bfloat162*)(ph + cb + 2) = __nv_bfloat162(h2, h3);
                *(__nv_bfloat162*)(pl + cb)     = __nv_bfloat162(
                    __float2bfloat16(v.x - __bfloat162float(h0)),
                    __float2bfloat16(v.y - __bfloat162float(h1)));
                *(__nv_bfloat162*)(pl + cb + 2) = __nv_bfloat162(
                    __float2bfloat16(v.z - __bfloat162float(h2)),
                    __float2bfloat16(v.w - __bfloat162float(h3)));
            }
        }
        __syncthreads();

        const uint32_t vb = smb + KV_OFF + (lt & 1) * KV_STG;
#pragma unroll
        for (int ks = 0; ks < 8; ++ks) {
            uint32_t fH[4], fL[4];
            uint32_t ao = (uint32_t)(arow * 136 + ks * 16 + acol) * 2;
            ldm_x4(fH, phB + ao);
            ldm_x4(fL, plB + ao);
            uint32_t vo = vb + (uint32_t)((ks * 16 + (lane & 15)) * 72 + wid * 8) * 2;
            uint32_t fVh[2], fVl[2];
            ldm_x2_t(fVh, vo);
            ldm_x2_t(fVl, vo + 18432);
            mma16816(cc, fH, fVh);
            mma16816(cc, fH, fVl);
            mma16816(cc, fL, fVh);
        }
        __syncthreads();
        if (lt + 2 < 16) { issueKV(Vh, Vl, lt + 2, lt & 1); CP_COMMIT(); }
    }

    // ---- ctx epilogue: write split bf16 (P already normalized) ----
    {
        int row = lane >> 2;
        int colp = (lane & 3) * 2;
        int b = bh >> 4, h = bh & 15;
        int n = h * 64 + wid * 8 + colp;
#pragma unroll
        for (int half = 0; half < 2; ++half) {
            int m = b * 2048 + q0 + row + half * 8;
            float v0 = cc[half * 2 + 0], v1 = cc[half * 2 + 1];
            __nv_bfloat16 h0 = __float2bfloat16(v0);
            __nv_bfloat16 h1 = __float2bfloat16(v1);
            *(__nv_bfloat162*)(ctxh + (size_t)m * D_ + n) = __nv_bfloat162(h0, h1);
            *(__nv_bfloat162*)(ctxl + (size_t)m * D_ + n) = __nv_bfloat162(
                __float2bfloat16(v0 - __bfloat162float(h0)),
                __float2bfloat16(v1 - __bfloat162float(h1)));
        }
    }
}

// ============================================================================
// host launcher
// ============================================================================
extern "C" void kernel_launch(void* const* d_in, const int* in_sizes, int n_in,
                              void* d_out, int out_size)
{
    const float* src = (const float*)d_in[0];
    const float* Wq  = (const float*)d_in[1];
    const float* bq  = (const float*)d_in[2];
    const float* Wk  = (const float*)d_in[3];
    const float* bk  = (const float*)d_in[4];
    const float* Wv  = (const float*)d_in[5];
    const float* bv  = (const float*)d_in[6];
    const float* Wo  = (const float*)d_in[7];
    const float* bo  = (const float*)d_in[8];
    const float* cw  = (const float*)d_in[9];
    const float* cb  = (const float*)d_in[10];

    float* out      = (float*)d_out;
    float* attn_out = out + OUT_ELEMS;

    float* salp;
    __nv_bfloat16 *Ahi, *Alo, *Whi, *Wlo;
    __nv_bfloat16 *Qh, *Ql, *Kh, *Kl, *Vh, *Vl;
    cudaGetSymbolAddress((void**)&salp, g_sal);
    cudaGetSymbolAddress((void**)&Ahi,  g_Ahi);
    cudaGetSymbolAddress((void**)&Alo,  g_Alo);
    cudaGetSymbolAddress((void**)&Whi,  g_Whi);
    cudaGetSymbolAddress((void**)&Wlo,  g_Wlo);
    cudaGetSymbolAddress((void**)&Qh,   g_Qh);
    cudaGetSymbolAddress((void**)&Ql,   g_Ql);
    cudaGetSymbolAddress((void**)&Kh,   g_Kh);
    cudaGetSymbolAddress((void**)&Kl,   g_Kl);
    cudaGetSymbolAddress((void**)&Vh,   g_Vh);
    cudaGetSymbolAddress((void**)&Vl,   g_Vl);

    cudaFuncSetAttribute(conv_sal_kernel,
        cudaFuncAttributeMaxDynamicSharedMemorySize, CONV_SMEM);
    cudaFuncSetAttribute(attn_kernel,
        cudaFuncAttributeMaxDynamicSharedMemorySize, ATTN_SMEM);
    cudaFuncSetAttribute(mma_gemm_bf16x3,
        cudaFuncAttributeMaxDynamicSharedMemorySize, GEMM_SMEM);

    // saliency conv
    conv_sal_kernel<<<B_ * 128, 256, CONV_SMEM>>>(src, cw, cb, salp);

    // bf16 hi/lo splits of src and weights
    const int WN4 = D_ * D_ / 4;
    cvt_split<<<(M_ * D_ / 4 + 255) / 256, 256>>>(src, Ahi, Alo, M_ * D_ / 4);
    cvt_split<<<(WN4 + 255) / 256, 256>>>(Wq, Whi + 0 * (size_t)D_ * D_, Wlo + 0 * (size_t)D_ * D_, WN4);
    cvt_split<<<(WN4 + 255) / 256, 256>>>(Wk, Whi + 1 * (size_t)D_ * D_, Wlo + 1 * (size_t)D_ * D_, WN4);
    cvt_split<<<(WN4 + 255) / 256, 256>>>(Wv, Whi + 2 * (size_t)D_ * D_, Wlo + 2 * (size_t)D_ * D_, WN4);
    cvt_split<<<(WN4 + 255) / 256, 256>>>(Wo, Whi + 3 * (size_t)D_ * D_, Wlo + 3 * (size_t)D_ * D_, WN4);

    // QKV projections (HMMA) -> split bf16 headed layout
    dim3 ggrid(8, 32);
    mma_gemm_bf16x3<<<ggrid, 256, GEMM_SMEM>>>(Ahi, Alo,
        Whi + 0 * (size_t)D_ * D_, Wlo + 0 * (size_t)D_ * D_, bq, nullptr, Qh, Ql, 1);
    mma_gemm_bf16x3<<<ggrid, 256, GEMM_SMEM>>>(Ahi, Alo,
        Whi + 1 * (size_t)D_ * D_, Wlo + 1 * (size_t)D_ * D_, bk, nullptr, Kh, Kl, 1);
    mma_gemm_bf16x3<<<ggrid, 256, GEMM_SMEM>>>(Ahi, Alo,
        Whi + 2 * (size_t)D_ * D_, Wlo + 2 * (size_t)D_ * D_, bv, nullptr, Vh, Vl, 1);

    // fused tensor-core attention (writes attn + ctx split into Ahi/Alo)
    dim3 agrid(L_ / 16, B_ * H_);
    attn_kernel<<<agrid, 256, ATTN_SMEM>>>(Qh, Ql, Kh, Kl, Vh, Vl, salp,
                                           Ahi, Alo, attn_out);

    // output projection (reads ctx split from Ahi/Alo) -> d_out
    mma_gemm_bf16x3<<<ggrid, 256, GEMM_SMEM>>>(Ahi, Alo,
        Whi + 3 * (size_t)D_ * D_, Wlo + 3 * (size_t)D_ * D_, bo, out, nullptr, nullptr, 0);
}

// round 8
// speedup vs baseline: 2.1602x; 1.0468x over previous
#include <cuda_runtime.h>
#include <cuda_bf16.h>
#include <cstdint>

#define B_ 2
#define L_ 2048
#define D_ 1024
#define H_ 16
#define DH_ 64
#define M_ (B_*L_)
#define OUT_ELEMS (B_*L_*D_)

// -------- scratch (static device arrays; no cudaMalloc allowed) --------
__device__ float g_sal[B_*H_*L_];
__device__ __nv_bfloat16 g_Ahi[M_*D_];
__device__ __nv_bfloat16 g_Alo[M_*D_];
__device__ __nv_bfloat16 g_Whi[4][D_*D_];
__device__ __nv_bfloat16 g_Wlo[4][D_*D_];
__device__ __nv_bfloat16 g_Qh[B_*H_*L_*DH_];
__device__ __nv_bfloat16 g_Ql[B_*H_*L_*DH_];
__device__ __nv_bfloat16 g_Kh[B_*H_*L_*DH_];
__device__ __nv_bfloat16 g_Kl[B_*H_*L_*DH_];
__device__ __nv_bfloat16 g_Vh[B_*H_*L_*DH_];
__device__ __nv_bfloat16 g_Vl[B_*H_*L_*DH_];

__device__ __forceinline__ uint32_t smem_u32(const void* p) {
    uint32_t a;
    asm("{ .reg .u64 t; cvta.to.shared.u64 t, %1; cvt.u32.u64 %0, t; }"
        : "=r"(a) : "l"(p));
    return a;
}

// -------- cp.async helpers --------
#define CP_ASYNC16(dst, src) \
    asm volatile("cp.async.cg.shared.global [%0], [%1], 16;" \
        :: "r"(dst), "l"(src))
#define CP_COMMIT() asm volatile("cp.async.commit_group;")
#define CP_WAIT1()  asm volatile("cp.async.wait_group 1;")
#define CP_WAIT0()  asm volatile("cp.async.wait_group 0;")

// -------- fast exp on the FMA pipe --------
__device__ __forceinline__ float fast_exp(float x) {
    x = fminf(fmaxf(x, -80.f), 80.f);
    float y = x * 1.4426950408889634f;
    float t = y + 12582912.0f;
    float n = t - 12582912.0f;
    float f = y - n;
    float p = 1.3333558146428443e-3f;
    p = fmaf(p, f, 9.6181291076284772e-3f);
    p = fmaf(p, f, 5.5504108664821580e-2f);
    p = fmaf(p, f, 2.4022650695910072e-1f);
    p = fmaf(p, f, 6.9314718055994531e-1f);
    p = fmaf(p, f, 1.0f);
    int ni = __float2int_rn(n);
    return __int_as_float(__float_as_int(p) + (ni << 23));
}

// ---------------- mma/ldmatrix primitives ----------------
__device__ __forceinline__ void ldm_x4(uint32_t* r, uint32_t addr) {
    asm volatile("ldmatrix.sync.aligned.m8n8.x4.shared.b16 {%0,%1,%2,%3}, [%4];"
        : "=r"(r[0]), "=r"(r[1]), "=r"(r[2]), "=r"(r[3]) : "r"(addr));
}
__device__ __forceinline__ void ldm_x2(uint32_t* r, uint32_t addr) {
    asm volatile("ldmatrix.sync.aligned.m8n8.x2.shared.b16 {%0,%1}, [%2];"
        : "=r"(r[0]), "=r"(r[1]) : "r"(addr));
}
__device__ __forceinline__ void ldm_x2_t(uint32_t* r, uint32_t addr) {
    asm volatile("ldmatrix.sync.aligned.m8n8.x2.trans.shared.b16 {%0,%1}, [%2];"
        : "=r"(r[0]), "=r"(r[1]) : "r"(addr));
}
__device__ __forceinline__ void mma16816(float* c, const uint32_t* a, const uint32_t* b) {
    asm volatile(
        "mma.sync.aligned.m16n8k16.row.col.f32.bf16.bf16.f32 "
        "{%0,%1,%2,%3}, {%4,%5,%6,%7}, {%8,%9}, {%0,%1,%2,%3};"
        : "+f"(c[0]), "+f"(c[1]), "+f"(c[2]), "+f"(c[3])
        : "r"(a[0]), "r"(a[1]), "r"(a[2]), "r"(a[3]), "r"(b[0]), "r"(b[1]));
}

// ============================================================================
// fp32 -> bf16 hi/lo split (vectorized)
// ============================================================================
__global__ void __launch_bounds__(256) cvt_split(
    const float* __restrict__ x, __nv_bfloat16* __restrict__ hi,
    __nv_bfloat16* __restrict__ lo, int n4)
{
    int i = blockIdx.x * blockDim.x + threadIdx.x;
    if (i >= n4) return;
    float4 v = ((const float4*)x)[i];
    __nv_bfloat16 h0 = __float2bfloat16(v.x);
    __nv_bfloat16 h1 = __float2bfloat16(v.y);
    __nv_bfloat16 h2 = __float2bfloat16(v.z);
    __nv_bfloat16 h3 = __float2bfloat16(v.w);
    __nv_bfloat162* hp = (__nv_bfloat162*)hi;
    __nv_bfloat162* lp = (__nv_bfloat162*)lo;
    hp[2 * i]     = __nv_bfloat162(h0, h1);
    hp[2 * i + 1] = __nv_bfloat162(h2, h3);
    lp[2 * i]     = __nv_bfloat162(__float2bfloat16(v.x - __bfloat162float(h0)),
                                   __float2bfloat16(v.y - __bfloat162float(h1)));
    lp[2 * i + 1] = __nv_bfloat162(__float2bfloat16(v.z - __bfloat162float(h2)),
                                   __float2bfloat16(v.w - __bfloat162float(h3)));
}

// 4 weights in one launch: grid.y selects the matrix
__global__ void __launch_bounds__(256) cvt_split_w(
    const float* __restrict__ w0, const float* __restrict__ w1,
    const float* __restrict__ w2, const float* __restrict__ w3,
    __nv_bfloat16* __restrict__ hi, __nv_bfloat16* __restrict__ lo)
{
    const int wsel = blockIdx.y;
    const float* x = (wsel == 0) ? w0 : (wsel == 1) ? w1 : (wsel == 2) ? w2 : w3;
    int i = blockIdx.x * blockDim.x + threadIdx.x;
    float4 v = ((const float4*)x)[i];
    size_t off = (size_t)wsel * (D_ * D_ / 2) + 2 * (size_t)i;
    __nv_bfloat16 h0 = __float2bfloat16(v.x);
    __nv_bfloat16 h1 = __float2bfloat16(v.y);
    __nv_bfloat16 h2 = __float2bfloat16(v.z);
    __nv_bfloat16 h3 = __float2bfloat16(v.w);
    ((__nv_bfloat162*)hi)[off]     = __nv_bfloat162(h0, h1);
    ((__nv_bfloat162*)hi)[off + 1] = __nv_bfloat162(h2, h3);
    ((__nv_bfloat162*)lo)[off]     = __nv_bfloat162(
        __float2bfloat16(v.x - __bfloat162float(h0)),
        __float2bfloat16(v.y - __bfloat162float(h1)));
    ((__nv_bfloat162*)lo)[off + 1] = __nv_bfloat162(
        __float2bfloat16(v.z - __bfloat162float(h2)),
        __float2bfloat16(v.w - __bfloat162float(h3)));
}

// ============================================================================
// mma.sync bf16x3 GEMM with cp.async double-buffered staging (unchanged R6)
// ============================================================================
#define TSTRIDE 40
#define GSTAGE 40960
#define GEMM_SMEM (2 * GSTAGE)

__global__ void __launch_bounds__(256) mma_gemm_bf16x3(
    const __nv_bfloat16* __restrict__ Ah, const __nv_bfloat16* __restrict__ Al,
    const __nv_bfloat16* __restrict__ Bh, const __nv_bfloat16* __restrict__ Bl,
    const float* __restrict__ bias, float* __restrict__ C,
    __nv_bfloat16* __restrict__ Ch, __nv_bfloat16* __restrict__ Cl, int headed)
{
    extern __shared__ __align__(128) char smg[];
    const uint32_t smb = smem_u32(smg);

    const int tid = threadIdx.x;
    const int wid = tid >> 5;
    const int lane = tid & 31;
    const int wm = (wid & 1) * 64;
    const int wn = (wid >> 1) * 32;
    const int m0 = blockIdx.y * 128;
    const int n0 = blockIdx.x * 128;

    float c[4][4][4];
#pragma unroll
    for (int i = 0; i < 4; ++i)
#pragma unroll
        for (int j = 0; j < 4; ++j)
#pragma unroll
            for (int r = 0; r < 4; ++r) c[i][j][r] = 0.f;

    auto issue = [&](int i, int st) {
        const int k0 = i * 32;
        const uint32_t sb = smb + st * GSTAGE;
#pragma unroll
        for (int t = 0; t < 2; ++t) {
            int idx = t * 256 + tid;
            int row = idx >> 2, sub = idx & 3;
            uint32_t off = (uint32_t)(row * TSTRIDE + sub * 8) * 2;
            size_t ga = (size_t)(m0 + row) * D_ + k0 + sub * 8;
            size_t gb = (size_t)(n0 + row) * D_ + k0 + sub * 8;
            CP_ASYNC16(sb + off,         Ah + ga);
            CP_ASYNC16(sb + 10240 + off, Al + ga);
            CP_ASYNC16(sb + 20480 + off, Bh + gb);
            CP_ASYNC16(sb + 30720 + off, Bl + gb);
        }
    };

    const int arow = lane & 15, acol = (lane >> 4) << 3;
    const int brow = lane & 7,  bcol = ((lane >> 3) & 1) << 3;

    issue(0, 0); CP_COMMIT();
    issue(1, 1); CP_COMMIT();

    for (int i = 0; i < 32; ++i) {
        if (i < 31) CP_WAIT1(); else CP_WAIT0();
        __syncthreads();
        const uint32_t aB = smb + (i & 1) * GSTAGE;

#pragma unroll
        for (int ks = 0; ks < 2; ++ks) {
            const int kk = ks * 16;
            uint32_t ah[4][4], al[4][4];
#pragma unroll
            for (int mt = 0; mt < 4; ++mt) {
                uint32_t off = (uint32_t)((wm + mt * 16 + arow) * TSTRIDE + kk + acol) * 2;
                ldm_x4(ah[mt], aB + off);
                ldm_x4(al[mt], aB + 10240 + off);
            }
#pragma unroll
            for (int nt = 0; nt < 4; ++nt) {
                uint32_t boff = (uint32_t)((wn + nt * 8 + brow) * TSTRIDE + kk + bcol) * 2;
                uint32_t bh[2], bl[2];
                ldm_x2(bh, aB + 20480 + boff);
                ldm_x2(bl, aB + 30720 + boff);
#pragma unroll
                for (int mt = 0; mt < 4; ++mt) {
                    mma16816(c[mt][nt], ah[mt], bh);
                    mma16816(c[mt][nt], ah[mt], bl);
                    mma16816(c[mt][nt], al[mt], bh);
                }
            }
        }
        __syncthreads();
        if (i + 2 < 32) { issue(i + 2, i & 1); CP_COMMIT(); }
    }

    const int rl = lane >> 2;
    const int cl = (lane & 3) * 2;
#pragma unroll
    for (int mt = 0; mt < 4; ++mt) {
#pragma unroll
        for (int half = 0; half < 2; ++half) {
            int m = m0 + wm + mt * 16 + rl + half * 8;
            int b = m >> 11, l = m & 2047;
#pragma unroll
            for (int nt = 0; nt < 4; ++nt) {
                int n = n0 + wn + nt * 8 + cl;
                float v0 = c[mt][nt][half * 2 + 0] + bias[n];
                float v1 = c[mt][nt][half * 2 + 1] + bias[n + 1];
                if (!headed) {
                    *(float2*)(C + (size_t)m * D_ + n) = make_float2(v0, v1);
                } else {
                    int h = n >> 6, dh = n & 63;
                    size_t off = (size_t)(((b << 4) + h) * 2048 + l) * 64 + dh;
                    __nv_bfloat16 h0 = __float2bfloat16(v0);
                    __nv_bfloat16 h1 = __float2bfloat16(v1);
                    *(__nv_bfloat162*)(Ch + off) = __nv_bfloat162(h0, h1);
                    *(__nv_bfloat162*)(Cl + off) = __nv_bfloat162(
                        __float2bfloat16(v0 - __bfloat162float(h0)),
                        __float2bfloat16(v1 - __bfloat162float(h1)));
                }
            }
        }
    }
}

// ============================================================================
// Saliency Conv1d(D->H, k=3, pad=1): sal[b,h,l]
// ============================================================================
#define CONV_SMEM (18 * 1028 * 4)
__global__ void __launch_bounds__(256) conv_sal_kernel(
    const float* __restrict__ src, const float* __restrict__ cw,
    const float* __restrict__ cb, float* __restrict__ sal)
{
    extern __shared__ float ss[];
    const int bid = blockIdx.x;
    const int b = bid >> 7, lt = bid & 127;
    const int l0 = lt * 16;
    const int tid = threadIdx.x;

#pragma unroll
    for (int it = 0; it < 18; ++it) {
        int idx = it * 256 + tid;
        int row = idx >> 8;
        int c4 = idx & 255;
        int gl = l0 + row - 1;
        float4 v = make_float4(0.f, 0.f, 0.f, 0.f);
        if (gl >= 0 && gl < L_)
            v = *(const float4*)(src + ((size_t)b * L_ + gl) * D_ + c4 * 4);
        *(float4*)(ss + row * 1028 + c4 * 4) = v;
    }
    __syncthreads();

    const int h = tid >> 4, li = tid & 15;
    const float* wp = cw + (size_t)h * D_ * 3;
    float acc = 0.f;
#pragma unroll 4
    for (int d = 0; d < D_; ++d) {
        float w0 = wp[d * 3 + 0], w1 = wp[d * 3 + 1], w2 = wp[d * 3 + 2];
        acc = fmaf(ss[(li + 0) * 1028 + d], w0, acc);
        acc = fmaf(ss[(li + 1) * 1028 + d], w1, acc);
        acc = fmaf(ss[(li + 2) * 1028 + d], w2, acc);
    }
    sal[(size_t)(b * H_ + h) * L_ + l0 + li] = acc + cb[h];
}

// ============================================================================
// Fused tensor-core attention, 512 threads (16 warps):
//  Phase1: 16 warps x 1 n8-strip; S = exp(QK^T/8+sal) stored DIRECTLY as
//          split bf16 Ph/Pl (no fp32 S tile, no pack pass); row sums in regs.
//  Phase2: warps split k in half (w, w+8 partner on same n8); attn written
//          from (Ph+Pl)*inv; 3-term PV HMMA; ctx partials reduced via smem.
// SMEM (bytes):
//  Ph 16x2056 bf16 @ 0        65,792
//  Pl              @ 65,792   65,792
//  K/V stages 2x   @ 131,584  73,728   (per stage: hi @0, lo @18,432)
//  sal fp32 2048   @ 205,312  8,192    (reused as ctx-reduction in epilogue)
//  Q (Qh,Ql 16x72) @ 213,504  4,608
//  sum 16x16 f32   @ 218,112  1,024
//  inv 16 f32      @ 219,136  64
// ============================================================================
#define PH_PITCH 2056
#define PL_OFF  65792
#define KV_OFF  131584
#define KV_STG  36864
#define SAL_OFF 205312
#define RED_OFF 205312
#define Q_OFF   213504
#define SUM_OFF 218112
#define INV_OFF 219136
#define ATTN_SMEM 219200

__global__ void __launch_bounds__(512) attn_kernel(
    const __nv_bfloat16* __restrict__ Qh, const __nv_bfloat16* __restrict__ Ql,
    const __nv_bfloat16* __restrict__ Kh, const __nv_bfloat16* __restrict__ Kl,
    const __nv_bfloat16* __restrict__ Vh, const __nv_bfloat16* __restrict__ Vl,
    const float* __restrict__ sal,
    __nv_bfloat16* __restrict__ ctxh, __nv_bfloat16* __restrict__ ctxl,
    float* __restrict__ attn)
{
    extern __shared__ __align__(128) char smem[];
    __nv_bfloat16* sPh = (__nv_bfloat16*)smem;
    __nv_bfloat16* sPl = (__nv_bfloat16*)(smem + PL_OFF);
    float* sSal = (float*)(smem + SAL_OFF);
    float* sSum = (float*)(smem + SUM_OFF);
    float* sInv = (float*)(smem + INV_OFF);
    const uint32_t smb = smem_u32(smem);
    const uint32_t phB = smb;
    const uint32_t plB = smb + PL_OFF;

    const int tid = threadIdx.x;
    const int wid = tid >> 5;
    const int lane = tid & 31;
    const int q0 = blockIdx.x * 16;
    const int bh = blockIdx.y;
    const size_t base = (size_t)bh * (L_ * DH_);

    // stage sal row (512 float4) + Q tile
    {
        const float4* gs = (const float4*)(sal + (size_t)bh * L_);
        ((float4*)sSal)[tid] = gs[tid];
        if (tid < 256) {
            int idx = tid & 127;
            int r = idx >> 3, s = idx & 7;
            const uint4* gq = (const uint4*)((tid < 128 ? Qh : Ql) + base + (size_t)q0 * DH_);
            __nv_bfloat16* dq = (__nv_bfloat16*)(smem + Q_OFF) + (tid < 128 ? 0 : 16 * 72);
            *(uint4*)(dq + r * 72 + s * 8) = gq[idx];
        }
    }
    __syncthreads();

    // preload Q fragments (m16 x k64, hi + lo)
    const int arow = lane & 15, acol = (lane >> 4) << 3;
    const int brow = lane & 7,  bcol = ((lane >> 3) & 1) << 3;
    uint32_t fQh[4][4], fQl[4][4];
    {
        const uint32_t qhB = smb + Q_OFF;
        const uint32_t qlB = qhB + 16 * 72 * 2;
#pragma unroll
        for (int ks = 0; ks < 4; ++ks) {
            uint32_t off = (uint32_t)(arow * 72 + ks * 16 + acol) * 2;
            ldm_x4(fQh[ks], qhB + off);
            ldm_x4(fQl[ks], qlB + off);
        }
    }

    auto issueKV = [&](const __nv_bfloat16* gh, const __nv_bfloat16* gl,
                       int t128, int st) {
        const uint32_t sb = smb + KV_OFF + st * KV_STG;
        const __nv_bfloat16* ph = gh + base + (size_t)t128 * 128 * DH_;
        const __nv_bfloat16* pl = gl + base + (size_t)t128 * 128 * DH_;
#pragma unroll
        for (int t = 0; t < 2; ++t) {
            int idx = t * 512 + tid;
            int r = idx >> 3, s = idx & 7;
            uint32_t off = (uint32_t)(r * 72 + s * 8) * 2;
            CP_ASYNC16(sb + off,         ph + (size_t)r * DH_ + s * 8);
            CP_ASYNC16(sb + 18432 + off, pl + (size_t)r * DH_ + s * 8);
        }
    };

    // ---- Phase 1: S = exp(QK^T/8 + sal) -> split bf16 Ph/Pl ----
    issueKV(Kh, Kl, 0, 0); CP_COMMIT();
    issueKV(Kh, Kl, 1, 1); CP_COMMIT();

    float sum_lo = 0.f, sum_hi = 0.f;
    const int row4 = lane >> 2;
    for (int kt = 0; kt < 16; ++kt) {
        if (kt < 15) CP_WAIT1(); else CP_WAIT0();
        __syncthreads();
        const uint32_t kb = smb + KV_OFF + (kt & 1) * KV_STG;

        float c[4] = {0.f, 0.f, 0.f, 0.f};
        uint32_t bo = kb + (uint32_t)((wid * 8 + brow) * 72 + bcol) * 2;
#pragma unroll
        for (int ks = 0; ks < 4; ++ks) {
            uint32_t bhf[2], blf[2];
            ldm_x2(bhf, bo + ks * 32);
            ldm_x2(blf, bo + 18432 + ks * 32);
            mma16816(c, fQh[ks], bhf);
            mma16816(c, fQl[ks], bhf);
            mma16816(c, fQh[ks], blf);
        }
        int col = kt * 128 + wid * 8 + (lane & 3) * 2;
        float s0 = sSal[col], s1 = sSal[col + 1];
        float e0 = fast_exp(fmaf(c[0], 0.125f, s0));
        float e1 = fast_exp(fmaf(c[1], 0.125f, s1));
        float e2 = fast_exp(fmaf(c[2], 0.125f, s0));
        float e3 = fast_exp(fmaf(c[3], 0.125f, s1));
        __nv_bfloat16 h0 = __float2bfloat16(e0);
        __nv_bfloat16 h1 = __float2bfloat16(e1);
        __nv_bfloat16 h2 = __float2bfloat16(e2);
        __nv_bfloat16 h3 = __float2bfloat16(e3);
        *(__nv_bfloat162*)(sPh + row4 * PH_PITCH + col) = __nv_bfloat162(h0, h1);
        *(__nv_bfloat162*)(sPl + row4 * PH_PITCH + col) = __nv_bfloat162(
            __float2bfloat16(e0 - __bfloat162float(h0)),
            __float2bfloat16(e1 - __bfloat162float(h1)));
        *(__nv_bfloat162*)(sPh + (row4 + 8) * PH_PITCH + col) = __nv_bfloat162(h2, h3);
        *(__nv_bfloat162*)(sPl + (row4 + 8) * PH_PITCH + col) = __nv_bfloat162(
            __float2bfloat16(e2 - __bfloat162float(h2)),
            __float2bfloat16(e3 - __bfloat162float(h3)));
        sum_lo += e0 + e1;
        sum_hi += e2 + e3;
        __syncthreads();
        if (kt + 2 < 16) { issueKV(Kh, Kl, kt + 2, kt & 1); CP_COMMIT(); }
    }

    // start V pipeline
    issueKV(Vh, Vl, 0, 0); CP_COMMIT();
    issueKV(Vh, Vl, 1, 1); CP_COMMIT();

    // ---- row-sum reduction -> sInv ----
    sum_lo += __shfl_xor_sync(0xffffffffu, sum_lo, 1);
    sum_lo += __shfl_xor_sync(0xffffffffu, sum_lo, 2);
    sum_hi += __shfl_xor_sync(0xffffffffu, sum_hi, 1);
    sum_hi += __shfl_xor_sync(0xffffffffu, sum_hi, 2);
    if ((lane & 3) == 0) {
        sSum[row4 * 16 + wid] = sum_lo;
        sSum[(row4 + 8) * 16 + wid] = sum_hi;
    }
    __syncthreads();
    if (tid < 16) {
        float s = 0.f;
#pragma unroll
        for (int j = 0; j < 16; ++j) s += sSum[tid * 16 + j];
        sInv[tid] = 1.f / s;
    }
    __syncthreads();

    // ---- Phase 2: attn write + 3-term PV (k split across warp pairs) ----
    const int n8p = wid & 7;
    const int kh = wid >> 3;
    float cc[4] = {0.f, 0.f, 0.f, 0.f};

    for (int lt = 0; lt < 16; ++lt) {
        if (lt < 15) CP_WAIT1(); else CP_WAIT0();
        __syncthreads();

        // attn write: one warp per row, reconstruct (hi+lo)*inv
        {
            int row = wid;
            float inv = sInv[row];
            int c0 = lt * 128 + lane * 4;
            __nv_bfloat162 a0 = *(const __nv_bfloat162*)(sPh + row * PH_PITCH + c0);
            __nv_bfloat162 a1 = *(const __nv_bfloat162*)(sPh + row * PH_PITCH + c0 + 2);
            __nv_bfloat162 b0 = *(const __nv_bfloat162*)(sPl + row * PH_PITCH + c0);
            __nv_bfloat162 b1 = *(const __nv_bfloat162*)(sPl + row * PH_PITCH + c0 + 2);
            float4 v;
            v.x = (__bfloat162float(a0.x) + __bfloat162float(b0.x)) * inv;
            v.y = (__bfloat162float(a0.y) + __bfloat162float(b0.y)) * inv;
            v.z = (__bfloat162float(a1.x) + __bfloat162float(b1.x)) * inv;
            v.w = (__bfloat162float(a1.y) + __bfloat162float(b1.y)) * inv;
            *(float4*)(attn + ((size_t)bh * L_ + q0 + row) * L_ + c0) = v;
        }

        const uint32_t vb = smb + KV_OFF + (lt & 1) * KV_STG;
#pragma unroll
        for (int ksl = 0; ksl < 4; ++ksl) {
            int ks = kh * 4 + ksl;
            int kp = lt * 128 + ks * 16;
            uint32_t fH[4], fL[4];
            uint32_t ao = (uint32_t)(arow * PH_PITCH + kp + acol) * 2;
            ldm_x4(fH, phB + ao);
            ldm_x4(fL, plB + ao);
            uint32_t vo = vb + (uint32_t)((ks * 16 + (lane & 15)) * 72 + n8p * 8) * 2;
            uint32_t fVh[2], fVl[2];
            ldm_x2_t(fVh, vo);
            ldm_x2_t(fVl, vo + 18432);
            mma16816(cc, fH, fVh);
            mma16816(cc, fH, fVl);
            mma16816(cc, fL, fVh);
        }
        __syncthreads();
        if (lt + 2 < 16) { issueKV(Vh, Vl, lt + 2, lt & 1); CP_COMMIT(); }
    }

    // ---- reduce ctx partials across warp pairs, write split bf16 ----
    float* red = (float*)(smem + RED_OFF);
    *(float4*)(red + wid * 128 + lane * 4) = make_float4(cc[0], cc[1], cc[2], cc[3]);
    __syncthreads();
    if (wid < 8) {
        float4 p = *(const float4*)(red + wid * 128 + lane * 4);
        float4 q = *(const float4*)(red + (wid + 8) * 128 + lane * 4);
        float v[4] = {p.x + q.x, p.y + q.y, p.z + q.z, p.w + q.w};
        // normalize by row sum
        int row = lane >> 2;
        int colp = (lane & 3) * 2;
        int b = bh >> 4, h = bh & 15;
        int n = h * 64 + wid * 8 + colp;
#pragma unroll
        for (int half = 0; half < 2; ++half) {
            int r = row + half * 8;
            float inv = sInv[r];
            int m = b * 2048 + q0 + r;
            float v0 = v[half * 2 + 0] * inv, v1 = v[half * 2 + 1] * inv;
            __nv_bfloat16 h0 = __float2bfloat16(v0);
            __nv_bfloat16 h1 = __float2bfloat16(v1);
            *(__nv_bfloat162*)(ctxh + (size_t)m * D_ + n) = __nv_bfloat162(h0, h1);
            *(__nv_bfloat162*)(ctxl + (size_t)m * D_ + n) = __nv_bfloat162(
                __float2bfloat16(v0 - __bfloat162float(h0)),
                __float2bfloat16(v1 - __bfloat162float(h1)));
        }
    }
}

// ============================================================================
// host launcher
// ============================================================================
extern "C" void kernel_launch(void* const* d_in, const int* in_sizes, int n_in,
                              void* d_out, int out_size)
{
    const float* src = (const float*)d_in[0];
    const float* Wq  = (const float*)d_in[1];
    const float* bq  = (const float*)d_in[2];
    const float* Wk  = (const float*)d_in[3];
    const float* bk  = (const float*)d_in[4];
    const float* Wv  = (const float*)d_in[5];
    const float* bv  = (const float*)d_in[6];
    const float* Wo  = (const float*)d_in[7];
    const float* bo  = (const float*)d_in[8];
    const float* cw  = (const float*)d_in[9];
    const float* cb  = (const float*)d_in[10];

    float* out      = (float*)d_out;
    float* attn_out = out + OUT_ELEMS;

    float* salp;
    __nv_bfloat16 *Ahi, *Alo, *Whi, *Wlo;
    __nv_bfloat16 *Qh, *Ql, *Kh, *Kl, *Vh, *Vl;
    cudaGetSymbolAddress((void**)&salp, g_sal);
    cudaGetSymbolAddress((void**)&Ahi,  g_Ahi);
    cudaGetSymbolAddress((void**)&Alo,  g_Alo);
    cudaGetSymbolAddress((void**)&Whi,  g_Whi);
    cudaGetSymbolAddress((void**)&Wlo,  g_Wlo);
    cudaGetSymbolAddress((void**)&Qh,   g_Qh);
    cudaGetSymbolAddress((void**)&Ql,   g_Ql);
    cudaGetSymbolAddress((void**)&Kh,   g_Kh);
    cudaGetSymbolAddress((void**)&Kl,   g_Kl);
    cudaGetSymbolAddress((void**)&Vh,   g_Vh);
    cudaGetSymbolAddress((void**)&Vl,   g_Vl);

    cudaFuncSetAttribute(conv_sal_kernel,
        cudaFuncAttributeMaxDynamicSharedMemorySize, CONV_SMEM);
    cudaFuncSetAttribute(attn_kernel,
        cudaFuncAttributeMaxDynamicSharedMemorySize, ATTN_SMEM);
    cudaFuncSetAttribute(mma_gemm_bf16x3,
        cudaFuncAttributeMaxDynamicSharedMemorySize, GEMM_SMEM);

    // saliency conv
    conv_sal_kernel<<<B_ * 128, 256, CONV_SMEM>>>(src, cw, cb, salp);

    // bf16 hi/lo splits: src + all 4 weights (one launch)
    cvt_split<<<(M_ * D_ / 4 + 255) / 256, 256>>>(src, Ahi, Alo, M_ * D_ / 4);
    dim3 wgrid(D_ * D_ / 4 / 256, 4);
    cvt_split_w<<<wgrid, 256>>>(Wq, Wk, Wv, Wo, Whi, Wlo);

    // QKV projections (HMMA) -> split bf16 headed layout
    dim3 ggrid(8, 32);
    mma_gemm_bf16x3<<<ggrid, 256, GEMM_SMEM>>>(Ahi, Alo,
        Whi + 0 * (size_t)D_ * D_, Wlo + 0 * (size_t)D_ * D_, bq, nullptr, Qh, Ql, 1);
    mma_gemm_bf16x3<<<ggrid, 256, GEMM_SMEM>>>(Ahi, Alo,
        Whi + 1 * (size_t)D_ * D_, Wlo + 1 * (size_t)D_ * D_, bk, nullptr, Kh, Kl, 1);
    mma_gemm_bf16x3<<<ggrid, 256, GEMM_SMEM>>>(Ahi, Alo,
        Whi + 2 * (size_t)D_ * D_, Wlo + 2 * (size_t)D_ * D_, bv, nullptr, Vh, Vl, 1);

    // fused tensor-core attention (writes attn + ctx split into Ahi/Alo)
    dim3 agrid(L_ / 16, B_ * H_);
    attn_kernel<<<agrid, 512, ATTN_SMEM>>>(Qh, Ql, Kh, Kl, Vh, Vl, salp,
                                           Ahi, Alo, attn_out);

    // output projection (reads ctx split from Ahi/Alo) -> d_out
    mma_gemm_bf16x3<<<ggrid, 256, GEMM_SMEM>>>(Ahi, Alo,
        Whi + 3 * (size_t)D_ * D_, Wlo + 3 * (size_t)D_ * D_, bo, out, nullptr, nullptr, 0);
}